// round 3
// baseline (speedup 1.0000x reference)
#include <cuda_runtime.h>
#include <math.h>
#include <stdint.h>

// ---------------- problem constants ----------------
#define BB   2
#define N1L  2048
#define N2L  128
#define TT   2176          // N1 + N2
#define DD   1024
#define HH   16
#define DHH  64
#define ND3  3072          // 3*D
#define NKT  34            // T/64 kv tiles
#define QTR  128           // q rows per attn block
#define NQT  17            // T/128 q tiles

// ---------------- scratch (__device__ globals; no allocs allowed) ----------------
__device__ float g_qkv[BB * TT * ND3];        // [B, T, 3*D]
__device__ float g_q[BB * HH * TT * DHH];     // [B,H,T,64]  (1/8 scale folded)
__device__ float g_k[BB * HH * TT * DHH];
__device__ float g_v[BB * HH * TT * DHH];
__device__ float g_x[BB * TT * DD];           // attention output, heads merged

// ---------------- helpers ----------------
__device__ __forceinline__ float to_tf32(float x) {
    uint32_t u;
    asm("cvt.rna.tf32.f32 %0, %1;" : "=r"(u) : "f"(x));
    return __uint_as_float(u);
}

__device__ __forceinline__ void mma_tf32(float* c, const float* a, const float* b) {
    asm volatile(
        "mma.sync.aligned.m16n8k8.row.col.f32.tf32.tf32.f32 "
        "{%0,%1,%2,%3}, {%4,%5,%6,%7}, {%8,%9}, {%0,%1,%2,%3};"
        : "+f"(c[0]), "+f"(c[1]), "+f"(c[2]), "+f"(c[3])
        : "r"(__float_as_uint(a[0])), "r"(__float_as_uint(a[1])),
          "r"(__float_as_uint(a[2])), "r"(__float_as_uint(b[0])),
          "r"(__float_as_uint(b[1])) , "r"(__float_as_uint(a[3])));
}

// NOTE: careful with operand order — use explicit wrapper below instead.
__device__ __forceinline__ void mma_tf32_v(float* c, const float a0, const float a1,
                                           const float a2, const float a3,
                                           const float b0, const float b1) {
    asm volatile(
        "mma.sync.aligned.m16n8k8.row.col.f32.tf32.tf32.f32 "
        "{%0,%1,%2,%3}, {%4,%5,%6,%7}, {%8,%9}, {%0,%1,%2,%3};"
        : "+f"(c[0]), "+f"(c[1]), "+f"(c[2]), "+f"(c[3])
        : "r"(__float_as_uint(a0)), "r"(__float_as_uint(a1)),
          "r"(__float_as_uint(a2)), "r"(__float_as_uint(a3)),
          "r"(__float_as_uint(b0)), "r"(__float_as_uint(b1)));
}

// =====================================================================
// tf32 tensor-core SGEMM with fragment-packed smem + double buffering.
// BM=128, BN=128, BK=16; 256 threads = 8 warps of 64x32 warp-tiles.
// C[remap_c(r)] = A[remap_a(r)] @ W + bias
// =====================================================================
// A packed: word ((ks*8+mblk)*32 + (r&7)*4 + (k&3))*4 + ((r>>3)&1) + 2*((k>>2)&1)
// B packed: word ((ks*16+nblk)*32 + (n&7)*4 + (k&3))*2 + ((k>>2)&1)
#define APW (2 * 8 * 32 * 4)     // 2048 floats per buffer
#define BPW (2 * 16 * 32 * 2)    // 2048 floats per buffer
__global__ __launch_bounds__(256) void sgemm_tf32(
    const float* __restrict__ A, const float* __restrict__ W,
    const float* __restrict__ bias, float* __restrict__ C,
    int M, int N, int K,
    int a_per, int a_base, int a_span,
    int c_per, int c_base, int c_span)
{
    __shared__ float Ap[2][APW];
    __shared__ float Bp[2][BPW];

    int tid = threadIdx.x;
    int bm = blockIdx.y, bn = blockIdx.x;
    int warp = tid >> 5, lane = tid & 31;
    int g = lane >> 2, tig = lane & 3;
    int wmb = (warp >> 2) * 4;          // mblk base (x16 rows)
    int wnb = (warp & 3) * 4;           // nblk base (x8 cols)

    // A global mapping: rows tid>>2 and +64, k-quad kq=(tid&3)
    int a_row0 = tid >> 2;
    int kq = tid & 3;
    const float* a_ptr[2];
#pragma unroll
    for (int i = 0; i < 2; i++) {
        int gr = bm * 128 + a_row0 + i * 64;
        int arow = (gr / a_per) * a_span + a_base + (gr % a_per);
        a_ptr[i] = A + (size_t)arow * K + kq * 4;
    }
    // A store base words (per i): ((ks*8+mblk)*32 + (r&7)*4)*4 + rh + 2*ch, +j*4 per elem
    int a_st[2];
#pragma unroll
    for (int i = 0; i < 2; i++) {
        int r = a_row0 + i * 64;
        a_st[i] = (((kq >> 1) * 8 + (r >> 4)) * 32 + (r & 7) * 4) * 4 + ((r >> 3) & 1) + 2 * (kq & 1);
    }

    // B global mapping: k-rows tid>>5 and +8, cols n0=(tid&31)*4
    int b_kr0 = tid >> 5;
    int b_n0 = (tid & 31) * 4;
    const float* b_ptr[2];
    int b_st[2];
#pragma unroll
    for (int i = 0; i < 2; i++) {
        int kr = b_kr0 + i * 8;
        b_ptr[i] = W + (size_t)kr * N + bn * 128 + b_n0;
        b_st[i] = (((kr >> 3) * 16 + (b_n0 >> 3)) * 32 + (b_n0 & 7) * 4 + (kr & 3)) * 2 + ((kr >> 2) & 1);
    }

    float acc[4][4][4];
#pragma unroll
    for (int mt = 0; mt < 4; mt++)
#pragma unroll
        for (int nt = 0; nt < 4; nt++)
#pragma unroll
            for (int r = 0; r < 4; r++) acc[mt][nt][r] = 0.f;

    int ntiles = K >> 4;

    // preload tile 0
    float4 avA[2], avB[2];
#pragma unroll
    for (int i = 0; i < 2; i++) {
        avA[i] = *(const float4*)(a_ptr[i]);
        avB[i] = *(const float4*)(b_ptr[i]);
    }
#pragma unroll
    for (int i = 0; i < 2; i++) {
        float* s = &Ap[0][a_st[i]];
        s[0]  = to_tf32(avA[i].x); s[4]  = to_tf32(avA[i].y);
        s[8]  = to_tf32(avA[i].z); s[12] = to_tf32(avA[i].w);
        float* t = &Bp[0][b_st[i]];
        t[0]  = to_tf32(avB[i].x); t[8]  = to_tf32(avB[i].y);
        t[16] = to_tf32(avB[i].z); t[24] = to_tf32(avB[i].w);
    }
    __syncthreads();

    for (int t = 0; t < ntiles; t++) {
        int cur = t & 1;
        // prefetch next
        if (t + 1 < ntiles) {
            int kk = (t + 1) * 16;
#pragma unroll
            for (int i = 0; i < 2; i++) {
                avA[i] = *(const float4*)(a_ptr[i] + kk);
                avB[i] = *(const float4*)(b_ptr[i] + (size_t)kk * N);
            }
        }
        // compute on cur
#pragma unroll
        for (int ks = 0; ks < 2; ks++) {
            float4 af[4]; float2 bf[4];
#pragma unroll
            for (int mt = 0; mt < 4; mt++)
                af[mt] = *(const float4*)&Ap[cur][(((ks * 8) + wmb + mt) * 32 + lane) * 4];
#pragma unroll
            for (int nt = 0; nt < 4; nt++)
                bf[nt] = *(const float2*)&Bp[cur][(((ks * 16) + wnb + nt) * 32 + lane) * 2];
#pragma unroll
            for (int mt = 0; mt < 4; mt++)
#pragma unroll
                for (int nt = 0; nt < 4; nt++)
                    mma_tf32_v(acc[mt][nt], af[mt].x, af[mt].y, af[mt].z, af[mt].w,
                               bf[nt].x, bf[nt].y);
        }
        // store next
        if (t + 1 < ntiles) {
            int nxt = cur ^ 1;
#pragma unroll
            for (int i = 0; i < 2; i++) {
                float* s = &Ap[nxt][a_st[i]];
                s[0]  = to_tf32(avA[i].x); s[4]  = to_tf32(avA[i].y);
                s[8]  = to_tf32(avA[i].z); s[12] = to_tf32(avA[i].w);
                float* tt = &Bp[nxt][b_st[i]];
                tt[0]  = to_tf32(avB[i].x); tt[8]  = to_tf32(avB[i].y);
                tt[16] = to_tf32(avB[i].z); tt[24] = to_tf32(avB[i].w);
            }
        }
        __syncthreads();
    }

    // Epilogue
#pragma unroll
    for (int mt = 0; mt < 4; mt++) {
        int gm0 = bm * 128 + (wmb + mt) * 16 + g;
        int gm1 = gm0 + 8;
        int cr0 = (gm0 / c_per) * c_span + c_base + (gm0 % c_per);
        int cr1 = (gm1 / c_per) * c_span + c_base + (gm1 % c_per);
#pragma unroll
        for (int nt = 0; nt < 4; nt++) {
            int cn = bn * 128 + (wnb + nt) * 8 + 2 * tig;
            float2 bi = *(const float2*)(bias + cn);
            *(float2*)(C + (size_t)cr0 * N + cn) =
                make_float2(acc[mt][nt][0] + bi.x, acc[mt][nt][1] + bi.y);
            *(float2*)(C + (size_t)cr1 * N + cn) =
                make_float2(acc[mt][nt][2] + bi.x, acc[mt][nt][3] + bi.y);
        }
    }
}

// =====================================================================
// RMSNorm(q,k) + scatter q/k/v from [B,T,3D] into [B,H,T,64].
// =====================================================================
__global__ __launch_bounds__(256) void rms_scatter_kernel(
    const float* __restrict__ gq1, const float* __restrict__ gk1,
    const float* __restrict__ gq2, const float* __restrict__ gk2)
{
    int warp = (blockIdx.x * blockDim.x + threadIdx.x) >> 5;
    int lane = threadIdx.x & 31;
    if (warp >= BB * TT * HH) return;
    int h = warp % HH;
    int bt = warp / HH;
    int t = bt % TT;
    int b = bt / TT;

    const float* base = g_qkv + (size_t)(b * TT + t) * ND3;
    const float* gq = (t < N1L) ? gq1 : gq2;
    const float* gk = (t < N1L) ? gk1 : gk2;

    int d0 = lane * 2;
    float2 qv = *(const float2*)(base + h * DHH + d0);
    float2 kv = *(const float2*)(base + DD + h * DHH + d0);
    float2 vv = *(const float2*)(base + 2 * DD + h * DHH + d0);

    float ssq = qv.x * qv.x + qv.y * qv.y;
    float ssk = kv.x * kv.x + kv.y * kv.y;
#pragma unroll
    for (int off = 16; off > 0; off >>= 1) {
        ssq += __shfl_xor_sync(0xffffffffu, ssq, off);
        ssk += __shfl_xor_sync(0xffffffffu, ssk, off);
    }
    float rq = rsqrtf(ssq * (1.f / 64.f) + 1e-6f) * 0.125f;
    float rk = rsqrtf(ssk * (1.f / 64.f) + 1e-6f);

    float2 gqv = *(const float2*)(gq + d0);
    float2 gkv = *(const float2*)(gk + d0);

    int o = ((b * HH + h) * TT + t) * DHH + d0;
    *(float2*)(g_q + o) = make_float2(qv.x * rq * gqv.x, qv.y * rq * gqv.y);
    *(float2*)(g_k + o) = make_float2(kv.x * rk * gkv.x, kv.y * rk * gkv.y);
    *(float2*)(g_v + o) = vv;
}

// =====================================================================
// Flash attention, tf32 mma, fragment-packed smem, register-resident P.
// grid = (17, B*H). 256 threads (8 warps), 128 q-rows/block, 64-kv tiles.
// Smem: Qp 32KB + Kp 16KB + Vp 16KB = 64KB dynamic.
// =====================================================================
#define QP_OFF 0
#define KP_OFF (8 * 8 * 32 * 4)            // 8192
#define VP_OFF (KP_OFF + 8 * 8 * 32 * 2)   // 12288
__global__ __launch_bounds__(256, 2) void attn_kernel()
{
    extern __shared__ float sm[];
    float* Qp = sm + QP_OFF;
    float* Kp = sm + KP_OFF;
    float* Vp = sm + VP_OFF;

    int qt = blockIdx.x;                // 0..16
    int bh = blockIdx.y;                // 0..31
    int tid = threadIdx.x;
    int warp = tid >> 5, lane = tid & 31;
    int g = lane >> 2, tig = lane & 3;

    const float* Qg = g_q + (size_t)(bh * TT + qt * QTR) * DHH;
    const float* Kg = g_k + (size_t)bh * TT * DHH;
    const float* Vg = g_v + (size_t)bh * TT * DHH;

    // ---- pack Q once: element (r,d) -> Qp[((d>>3)*8 + (r>>4))*32 + (r&7)*4+(d&3)]*4
    //      + ((r>>3)&1) + 2*((d>>2)&1)
#pragma unroll
    for (int i = 0; i < 8; i++) {
        int idx = tid + i * 256;
        int r = idx >> 4, dq = (idx & 15) * 4;
        float4 v = *(const float4*)(Qg + r * DHH + dq);
        int slotbase = ((r >> 3) & 1) + 2 * ((dq >> 2) & 1);
        float* s = &Qp[((((dq >> 3) * 8) + (r >> 4)) * 32 + (r & 7) * 4) * 4 + slotbase];
        s[0]  = to_tf32(v.x);
        s[4]  = to_tf32(v.y);
        s[8]  = to_tf32(v.z);
        s[12] = to_tf32(v.w);
    }

    float S[8][4], O[8][4];
    float m_r[2], l_r[2];
#pragma unroll
    for (int nt = 0; nt < 8; nt++)
#pragma unroll
        for (int r = 0; r < 4; r++) O[nt][r] = 0.f;
    m_r[0] = m_r[1] = -1e30f;
    l_r[0] = l_r[1] = 0.f;

    for (int kt = 0; kt < NKT; kt++) {
        __syncthreads();   // prev compute done with Kp/Vp; Qp visible iter 0
        const float* Kt = Kg + kt * 64 * DHH;
        const float* Vt = Vg + kt * 64 * DHH;
        // K: element (n=r, k=d) -> Kp[((d>>3)*8 + (r>>3))*32 + (r&7)*4+(d&3)]*2 + ((d>>2)&1)
        // V: element (k=r, n=d) -> Vp[((r>>3)*8 + (d>>3))*32 + (d&7)*4+(r&3)]*2 + ((r>>2)&1)
#pragma unroll
        for (int i = 0; i < 4; i++) {
            int idx = tid + i * 256;
            int r = idx >> 4, dq = (idx & 15) * 4;
            float4 kv4 = *(const float4*)(Kt + r * DHH + dq);
            {
                int hi = (dq >> 2) & 1;
                float* s = &Kp[((((dq >> 3) * 8) + (r >> 3)) * 32 + (r & 7) * 4) * 2 + hi];
                s[0] = to_tf32(kv4.x);
                s[2] = to_tf32(kv4.y);
                s[4] = to_tf32(kv4.z);
                s[6] = to_tf32(kv4.w);
            }
            float4 vv4 = *(const float4*)(Vt + r * DHH + dq);
            {
                int hi = (r >> 2) & 1;
                int kc8 = (r >> 3) * 8;
                int tv = r & 3;
                // d = dq + j : nt = (dq+j)>>3 constant per quad? dq multiple of 4:
                // (d&7) = (dq&7)+j, nt = dq>>3 constant within the quad.
                float* s = &Vp[(((kc8 + (dq >> 3)) * 32) + (dq & 7) * 4 + tv) * 2 + hi];
                s[0] = to_tf32(vv4.x);
                s[8] = to_tf32(vv4.y);
                s[16] = to_tf32(vv4.z);
                s[24] = to_tf32(vv4.w);
            }
        }
        __syncthreads();

        // ---- S = Q . K^T  (warp: m16 x n64, k=64)
#pragma unroll
        for (int nt = 0; nt < 8; nt++)
#pragma unroll
            for (int r = 0; r < 4; r++) S[nt][r] = 0.f;
#pragma unroll
        for (int ks = 0; ks < 8; ks++) {
            float4 a = *(const float4*)&Qp[((ks * 8 + warp) * 32 + lane) * 4];
#pragma unroll
            for (int nt = 0; nt < 8; nt++) {
                float2 b = *(const float2*)&Kp[((ks * 8 + nt) * 32 + lane) * 2];
                mma_tf32_v(S[nt], a.x, a.y, a.z, a.w, b.x, b.y);
            }
        }

        float biasv = (qt < 16 && kt < 32 && (kt >> 2) > (qt >> 1)) ? 1.0f : 0.0f;

        // ---- online softmax; p written back into S regs
#pragma unroll
        for (int r = 0; r < 2; r++) {
            float mx = -1e30f;
#pragma unroll
            for (int nt = 0; nt < 8; nt++) {
                S[nt][2 * r]     += biasv;
                S[nt][2 * r + 1] += biasv;
                mx = fmaxf(mx, fmaxf(S[nt][2 * r], S[nt][2 * r + 1]));
            }
            mx = fmaxf(mx, __shfl_xor_sync(0xffffffffu, mx, 1));
            mx = fmaxf(mx, __shfl_xor_sync(0xffffffffu, mx, 2));
            float mn = fmaxf(m_r[r], mx);
            float rs = 0.f;
#pragma unroll
            for (int nt = 0; nt < 8; nt++) {
                float p0 = __expf(S[nt][2 * r]     - mn);
                float p1 = __expf(S[nt][2 * r + 1] - mn);
                S[nt][2 * r]     = p0;
                S[nt][2 * r + 1] = p1;
                rs += p0 + p1;
            }
            rs += __shfl_xor_sync(0xffffffffu, rs, 1);
            rs += __shfl_xor_sync(0xffffffffu, rs, 2);
            float alpha = __expf(m_r[r] - mn);
            l_r[r] = l_r[r] * alpha + rs;
            m_r[r] = mn;
#pragma unroll
            for (int nt = 0; nt < 8; nt++) {
                O[nt][2 * r]     *= alpha;
                O[nt][2 * r + 1] *= alpha;
            }
        }

        // ---- O += P . V : P A-fragments from S C-fragments via shuffles
        int l0 = (lane & 28) | (tig >> 1);
        int l1 = l0 + 2;
        bool odd = (tig & 1);
#pragma unroll
        for (int kc = 0; kc < 8; kc++) {
            float s0 = __shfl_sync(0xffffffffu, S[kc][0], l0);
            float s1 = __shfl_sync(0xffffffffu, S[kc][1], l0);
            float s2 = __shfl_sync(0xffffffffu, S[kc][2], l0);
            float s3 = __shfl_sync(0xffffffffu, S[kc][3], l0);
            float t0 = __shfl_sync(0xffffffffu, S[kc][0], l1);
            float t1 = __shfl_sync(0xffffffffu, S[kc][1], l1);
            float t2 = __shfl_sync(0xffffffffu, S[kc][2], l1);
            float t3 = __shfl_sync(0xffffffffu, S[kc][3], l1);
            float a0 = to_tf32(odd ? s1 : s0);
            float a1 = to_tf32(odd ? s3 : s2);
            float a2 = to_tf32(odd ? t1 : t0);
            float a3 = to_tf32(odd ? t3 : t2);
#pragma unroll
            for (int nt = 0; nt < 8; nt++) {
                float2 b = *(const float2*)&Vp[((kc * 8 + nt) * 32 + lane) * 2];
                mma_tf32_v(O[nt], a0, a1, a2, a3, b.x, b.y);
            }
        }
    }

    // ---- write out: g_x[b][t][h*64 + d]
    int b = bh / HH, h = bh % HH;
    float inv0 = 1.f / l_r[0], inv1 = 1.f / l_r[1];
    int t0 = qt * QTR + warp * 16 + g;
#pragma unroll
    for (int nt = 0; nt < 8; nt++) {
        int col = h * DHH + nt * 8 + 2 * tig;
        *(float2*)(g_x + (size_t)(b * TT + t0) * DD + col) =
            make_float2(O[nt][0] * inv0, O[nt][1] * inv0);
        *(float2*)(g_x + (size_t)(b * TT + t0 + 8) * DD + col) =
            make_float2(O[nt][2] * inv1, O[nt][3] * inv1);
    }
}

// =====================================================================
// Launch
// =====================================================================
extern "C" void kernel_launch(void* const* d_in, const int* in_sizes, int n_in,
                              void* d_out, int out_size)
{
    const float* x1    = (const float*)d_in[0];
    const float* x2    = (const float*)d_in[1];
    const float* Wqkv1 = (const float*)d_in[2];
    const float* bqkv1 = (const float*)d_in[3];
    const float* Wqkv2 = (const float*)d_in[4];
    const float* bqkv2 = (const float*)d_in[5];
    const float* Wout1 = (const float*)d_in[6];
    const float* bout1 = (const float*)d_in[7];
    const float* Wout2 = (const float*)d_in[8];
    const float* bout2 = (const float*)d_in[9];
    const float* gq1   = (const float*)d_in[10];
    const float* gk1   = (const float*)d_in[11];
    const float* gq2   = (const float*)d_in[12];
    const float* gk2   = (const float*)d_in[13];
    float* out = (float*)d_out;

    float* p_qkv = nullptr; float* p_x = nullptr;
    cudaGetSymbolAddress((void**)&p_qkv, g_qkv);
    cudaGetSymbolAddress((void**)&p_x, g_x);

    // QKV projections -> [B, T, 3D]
    sgemm_tf32<<<dim3(ND3 / 128, (BB * N1L) / 128), 256>>>(
        x1, Wqkv1, bqkv1, p_qkv, BB * N1L, ND3, DD,
        BB * N1L, 0, BB * N1L,
        N1L, 0, TT);
    sgemm_tf32<<<dim3(ND3 / 128, (BB * N2L) / 128), 256>>>(
        x2, Wqkv2, bqkv2, p_qkv, BB * N2L, ND3, DD,
        BB * N2L, 0, BB * N2L,
        N2L, N1L, TT);

    // RMSNorm + scatter to [B,H,T,64]
    rms_scatter_kernel<<<(BB * TT * HH * 32) / 256, 256>>>(gq1, gk1, gq2, gk2);

    // Attention: 64KB dynamic smem
    int smem = (8 * 8 * 32 * 4 + 2 * 8 * 8 * 32 * 2) * (int)sizeof(float);  // 65536
    cudaFuncSetAttribute(attn_kernel, cudaFuncAttributeMaxDynamicSharedMemorySize, smem);
    attn_kernel<<<dim3(NQT, BB * HH), 256, smem>>>();

    // Output projections
    sgemm_tf32<<<dim3(DD / 128, (BB * N1L) / 128), 256>>>(
        p_x, Wout1, bout1, out, BB * N1L, DD, DD,
        N1L, 0, TT,
        BB * N1L, 0, BB * N1L);
    sgemm_tf32<<<dim3(DD / 128, (BB * N2L) / 128), 256>>>(
        p_x, Wout2, bout2, out + (size_t)BB * N1L * DD, BB * N2L, DD, DD,
        N2L, N1L, TT,
        BB * N2L, 0, BB * N2L);
}

// round 4
// speedup vs baseline: 1.8366x; 1.8366x over previous
#include <cuda_runtime.h>
#include <math.h>
#include <stdint.h>

// ---------------- problem constants ----------------
#define BB   2
#define N1L  2048
#define N2L  128
#define TT   2176          // N1 + N2
#define DD   1024
#define HH   16
#define DHH  64
#define ND3  3072          // 3*D
#define NKT  34            // T/64 kv tiles
#define QTR  128           // q rows per attn block
#define NQT  17            // T/128 q tiles

// ---------------- scratch (__device__ globals; no allocs allowed) ----------------
__device__ float g_qkv[BB * TT * ND3];        // [B, T, 3*D]
__device__ float g_q[BB * HH * TT * DHH];     // [B,H,T,64]  (1/8 scale folded)
__device__ float g_k[BB * HH * TT * DHH];
__device__ float g_v[BB * HH * TT * DHH];
__device__ float g_x[BB * TT * DD];           // attention output, heads merged

// ---------------- helpers ----------------
__device__ __forceinline__ float to_tf32(float x) {
    uint32_t u;
    asm("cvt.rna.tf32.f32 %0, %1;" : "=r"(u) : "f"(x));
    return __uint_as_float(u);
}

__device__ __forceinline__ void mma_tf32_v(float* c, const float a0, const float a1,
                                           const float a2, const float a3,
                                           const float b0, const float b1) {
    asm volatile(
        "mma.sync.aligned.m16n8k8.row.col.f32.tf32.tf32.f32 "
        "{%0,%1,%2,%3}, {%4,%5,%6,%7}, {%8,%9}, {%0,%1,%2,%3};"
        : "+f"(c[0]), "+f"(c[1]), "+f"(c[2]), "+f"(c[3])
        : "r"(__float_as_uint(a0)), "r"(__float_as_uint(a1)),
          "r"(__float_as_uint(a2)), "r"(__float_as_uint(a3)),
          "r"(__float_as_uint(b0)), "r"(__float_as_uint(b1)));
}

// =====================================================================
// tf32 tensor-core SGEMM (R1 layout) + double buffering.
// BM=128, BN=128, BK=16; 256 threads = 8 warps of 64x32 warp-tiles.
// C[remap_c(r)] = A[remap_a(r)] @ W + bias
// =====================================================================
#define ALD 20     // As row stride
#define BLD 136    // Bs row stride
__global__ __launch_bounds__(256) void sgemm_tf32(
    const float* __restrict__ A, const float* __restrict__ W,
    const float* __restrict__ bias, float* __restrict__ C,
    int M, int N, int K,
    int a_per, int a_base, int a_span,
    int c_per, int c_base, int c_span)
{
    __shared__ float As[2][128 * ALD];
    __shared__ float Bs[2][16 * BLD];

    int tid = threadIdx.x;
    int bm = blockIdx.y, bn = blockIdx.x;
    int warp = tid >> 5, lane = tid & 31;
    int g = lane >> 2, tig = lane & 3;
    int wm = (warp >> 2) * 64, wn = (warp & 3) * 32;

    // A global: 2 float4 / thread (rows tid>>2 and +64, k-quad (tid&3)*4)
    int a_row[2], a_kq[2];
    const float* a_ptr[2];
#pragma unroll
    for (int i = 0; i < 2; i++) {
        int idx = tid + i * 256;
        a_row[i] = idx >> 2;
        a_kq[i]  = (idx & 3) * 4;
        int gr = bm * 128 + a_row[i];
        int arow = (gr / a_per) * a_span + a_base + (gr % a_per);
        a_ptr[i] = A + (size_t)arow * K + a_kq[i];
    }
    // B global: 2 float4 / thread (k-rows tid>>5 and +8, 4 cols)
    int b_kr[2], b_nq[2];
    const float* b_ptr[2];
#pragma unroll
    for (int i = 0; i < 2; i++) {
        int idx = tid + i * 256;
        b_kr[i] = idx >> 5;
        b_nq[i] = (idx & 31) * 4;
        b_ptr[i] = W + (size_t)b_kr[i] * N + bn * 128 + b_nq[i];
    }

    float acc[4][4][4];
#pragma unroll
    for (int mt = 0; mt < 4; mt++)
#pragma unroll
        for (int nt = 0; nt < 4; nt++)
#pragma unroll
            for (int r = 0; r < 4; r++) acc[mt][nt][r] = 0.f;

    int ntiles = K >> 4;

    // ---- preload tile 0 into buffer 0
    float4 av[2], bv[2];
#pragma unroll
    for (int i = 0; i < 2; i++) {
        av[i] = *(const float4*)(a_ptr[i]);
        bv[i] = *(const float4*)(b_ptr[i]);
    }
#pragma unroll
    for (int i = 0; i < 2; i++) {
        float* as = &As[0][a_row[i] * ALD + a_kq[i]];
        as[0] = to_tf32(av[i].x); as[1] = to_tf32(av[i].y);
        as[2] = to_tf32(av[i].z); as[3] = to_tf32(av[i].w);
        float* bs = &Bs[0][b_kr[i] * BLD + b_nq[i]];
        bs[0] = to_tf32(bv[i].x); bs[1] = to_tf32(bv[i].y);
        bs[2] = to_tf32(bv[i].z); bs[3] = to_tf32(bv[i].w);
    }
    __syncthreads();

    for (int t = 0; t < ntiles; t++) {
        int cur = t & 1;
        // prefetch next tile (global -> regs)
        if (t + 1 < ntiles) {
            int kk = (t + 1) * 16;
#pragma unroll
            for (int i = 0; i < 2; i++) {
                av[i] = *(const float4*)(a_ptr[i] + kk);
                bv[i] = *(const float4*)(b_ptr[i] + (size_t)kk * N);
            }
        }
        // compute on cur
#pragma unroll
        for (int ks = 0; ks < 16; ks += 8) {
            float afr[4][4], bfr[4][2];
#pragma unroll
            for (int mt = 0; mt < 4; mt++) {
                int rb = wm + mt * 16;
                afr[mt][0] = As[cur][(rb + g)     * ALD + ks + tig];
                afr[mt][1] = As[cur][(rb + g + 8) * ALD + ks + tig];
                afr[mt][2] = As[cur][(rb + g)     * ALD + ks + tig + 4];
                afr[mt][3] = As[cur][(rb + g + 8) * ALD + ks + tig + 4];
            }
#pragma unroll
            for (int nt = 0; nt < 4; nt++) {
                int nb = wn + nt * 8;
                bfr[nt][0] = Bs[cur][(ks + tig)     * BLD + nb + g];
                bfr[nt][1] = Bs[cur][(ks + tig + 4) * BLD + nb + g];
            }
#pragma unroll
            for (int mt = 0; mt < 4; mt++)
#pragma unroll
                for (int nt = 0; nt < 4; nt++)
                    mma_tf32_v(acc[mt][nt], afr[mt][0], afr[mt][1], afr[mt][2], afr[mt][3],
                               bfr[nt][0], bfr[nt][1]);
        }
        // store next tile (regs -> other buffer)
        if (t + 1 < ntiles) {
            int nxt = cur ^ 1;
#pragma unroll
            for (int i = 0; i < 2; i++) {
                float* as = &As[nxt][a_row[i] * ALD + a_kq[i]];
                as[0] = to_tf32(av[i].x); as[1] = to_tf32(av[i].y);
                as[2] = to_tf32(av[i].z); as[3] = to_tf32(av[i].w);
                float* bs = &Bs[nxt][b_kr[i] * BLD + b_nq[i]];
                bs[0] = to_tf32(bv[i].x); bs[1] = to_tf32(bv[i].y);
                bs[2] = to_tf32(bv[i].z); bs[3] = to_tf32(bv[i].w);
            }
        }
        __syncthreads();
    }

    // Epilogue
#pragma unroll
    for (int mt = 0; mt < 4; mt++) {
        int gm0 = bm * 128 + wm + mt * 16 + g;
        int gm1 = gm0 + 8;
        int cr0 = (gm0 / c_per) * c_span + c_base + (gm0 % c_per);
        int cr1 = (gm1 / c_per) * c_span + c_base + (gm1 % c_per);
#pragma unroll
        for (int nt = 0; nt < 4; nt++) {
            int cn = bn * 128 + wn + nt * 8 + 2 * tig;
            float2 bi = *(const float2*)(bias + cn);
            *(float2*)(C + (size_t)cr0 * N + cn) =
                make_float2(acc[mt][nt][0] + bi.x, acc[mt][nt][1] + bi.y);
            *(float2*)(C + (size_t)cr1 * N + cn) =
                make_float2(acc[mt][nt][2] + bi.x, acc[mt][nt][3] + bi.y);
        }
    }
}

// =====================================================================
// RMSNorm(q,k) + scatter q/k/v from [B,T,3D] into [B,H,T,64].
// =====================================================================
__global__ __launch_bounds__(256) void rms_scatter_kernel(
    const float* __restrict__ gq1, const float* __restrict__ gk1,
    const float* __restrict__ gq2, const float* __restrict__ gk2)
{
    int warp = (blockIdx.x * blockDim.x + threadIdx.x) >> 5;
    int lane = threadIdx.x & 31;
    if (warp >= BB * TT * HH) return;
    int h = warp % HH;
    int bt = warp / HH;
    int t = bt % TT;
    int b = bt / TT;

    const float* base = g_qkv + (size_t)(b * TT + t) * ND3;
    const float* gq = (t < N1L) ? gq1 : gq2;
    const float* gk = (t < N1L) ? gk1 : gk2;

    int d0 = lane * 2;
    float2 qv = *(const float2*)(base + h * DHH + d0);
    float2 kv = *(const float2*)(base + DD + h * DHH + d0);
    float2 vv = *(const float2*)(base + 2 * DD + h * DHH + d0);

    float ssq = qv.x * qv.x + qv.y * qv.y;
    float ssk = kv.x * kv.x + kv.y * kv.y;
#pragma unroll
    for (int off = 16; off > 0; off >>= 1) {
        ssq += __shfl_xor_sync(0xffffffffu, ssq, off);
        ssk += __shfl_xor_sync(0xffffffffu, ssk, off);
    }
    float rq = rsqrtf(ssq * (1.f / 64.f) + 1e-6f) * 0.125f;
    float rk = rsqrtf(ssk * (1.f / 64.f) + 1e-6f);

    float2 gqv = *(const float2*)(gq + d0);
    float2 gkv = *(const float2*)(gk + d0);

    int o = ((b * HH + h) * TT + t) * DHH + d0;
    *(float2*)(g_q + o) = make_float2(qv.x * rq * gqv.x, qv.y * rq * gqv.y);
    *(float2*)(g_k + o) = make_float2(kv.x * rk * gkv.x, kv.y * rk * gkv.y);
    *(float2*)(g_v + o) = vv;
}

// =====================================================================
// Flash attention, tf32 mma, R1 smem layouts, register-resident P.
// grid = (17, B*H). 256 threads (8 warps), 128 q-rows/block, 64-kv tiles.
// Smem: Qs [128][68] + Ks [64][72] + Vs [64][72] = 71680 B -> 2 CTAs/SM.
// =====================================================================
#define QLD 68     // Qs row stride
#define KLD 72     // Ks/Vs row stride
__global__ __launch_bounds__(256, 2) void attn_kernel()
{
    extern __shared__ float sm[];
    float* Qs = sm;                     // [128][68]  (q, d)
    float* Ks = Qs + QTR * QLD;         // [64][72]   (d, kv)  transposed
    float* Vs = Ks + 64 * KLD;          // [64][72]   (kv, d)

    int qt = blockIdx.x;                // 0..16
    int bh = blockIdx.y;                // 0..31
    int tid = threadIdx.x;
    int warp = tid >> 5, lane = tid & 31;
    int g = lane >> 2, tig = lane & 3;
    int mb = warp * 16;

    const float* Qg = g_q + (size_t)(bh * TT + qt * QTR) * DHH;
    const float* Kg = g_k + (size_t)bh * TT * DHH;
    const float* Vg = g_v + (size_t)bh * TT * DHH;

    // Load Q tile (tf32-rounded)
#pragma unroll
    for (int i = 0; i < 8; i++) {
        int idx = tid + i * 256;
        int r = idx >> 4, dq = (idx & 15) * 4;
        float4 v = *(const float4*)(Qg + r * DHH + dq);
        float* qs = &Qs[r * QLD + dq];
        qs[0] = to_tf32(v.x); qs[1] = to_tf32(v.y);
        qs[2] = to_tf32(v.z); qs[3] = to_tf32(v.w);
    }

    float S[8][4], O[8][4];
    float m_r[2], l_r[2];
#pragma unroll
    for (int nt = 0; nt < 8; nt++)
#pragma unroll
        for (int r = 0; r < 4; r++) O[nt][r] = 0.f;
    m_r[0] = m_r[1] = -1e30f;
    l_r[0] = l_r[1] = 0.f;

    for (int kt = 0; kt < NKT; kt++) {
        __syncthreads();   // prev PV done with Ks/Vs; Q visible on iter 0
        const float* Kt = Kg + kt * 64 * DHH;
        const float* Vt = Vg + kt * 64 * DHH;
#pragma unroll
        for (int i = 0; i < 4; i++) {
            int idx = tid + i * 256;
            int r = idx >> 4, dq = (idx & 15) * 4;
            float4 kv4 = *(const float4*)(Kt + r * DHH + dq);
            Ks[(dq + 0) * KLD + r] = to_tf32(kv4.x);
            Ks[(dq + 1) * KLD + r] = to_tf32(kv4.y);
            Ks[(dq + 2) * KLD + r] = to_tf32(kv4.z);
            Ks[(dq + 3) * KLD + r] = to_tf32(kv4.w);
            float4 vv4 = *(const float4*)(Vt + r * DHH + dq);
            float* vs = &Vs[r * KLD + dq];
            vs[0] = to_tf32(vv4.x); vs[1] = to_tf32(vv4.y);
            vs[2] = to_tf32(vv4.z); vs[3] = to_tf32(vv4.w);
        }
        __syncthreads();

        // ---- S = Q . K^T  (warp: m16 x n64, k=64)
#pragma unroll
        for (int nt = 0; nt < 8; nt++)
#pragma unroll
            for (int r = 0; r < 4; r++) S[nt][r] = 0.f;
#pragma unroll
        for (int ks = 0; ks < 8; ks++) {
            int k0 = ks * 8;
            float a0 = Qs[(mb + g)     * QLD + k0 + tig];
            float a1 = Qs[(mb + g + 8) * QLD + k0 + tig];
            float a2 = Qs[(mb + g)     * QLD + k0 + tig + 4];
            float a3 = Qs[(mb + g + 8) * QLD + k0 + tig + 4];
#pragma unroll
            for (int nt = 0; nt < 8; nt++) {
                float b0 = Ks[(k0 + tig)     * KLD + nt * 8 + g];
                float b1 = Ks[(k0 + tig + 4) * KLD + nt * 8 + g];
                mma_tf32_v(S[nt], a0, a1, a2, a3, b0, b1);
            }
        }

        float biasv = (qt < 16 && kt < 32 && (kt >> 2) > (qt >> 1)) ? 1.0f : 0.0f;

        // ---- online softmax; p kept in S regs
#pragma unroll
        for (int r = 0; r < 2; r++) {
            float mx = -1e30f;
#pragma unroll
            for (int nt = 0; nt < 8; nt++) {
                S[nt][2 * r]     += biasv;
                S[nt][2 * r + 1] += biasv;
                mx = fmaxf(mx, fmaxf(S[nt][2 * r], S[nt][2 * r + 1]));
            }
            mx = fmaxf(mx, __shfl_xor_sync(0xffffffffu, mx, 1));
            mx = fmaxf(mx, __shfl_xor_sync(0xffffffffu, mx, 2));
            float mn = fmaxf(m_r[r], mx);
            float rs = 0.f;
#pragma unroll
            for (int nt = 0; nt < 8; nt++) {
                float p0 = __expf(S[nt][2 * r]     - mn);
                float p1 = __expf(S[nt][2 * r + 1] - mn);
                S[nt][2 * r]     = p0;
                S[nt][2 * r + 1] = p1;
                rs += p0 + p1;
            }
            rs += __shfl_xor_sync(0xffffffffu, rs, 1);
            rs += __shfl_xor_sync(0xffffffffu, rs, 2);
            float alpha = __expf(m_r[r] - mn);
            l_r[r] = l_r[r] * alpha + rs;
            m_r[r] = mn;
#pragma unroll
            for (int nt = 0; nt < 8; nt++) {
                O[nt][2 * r]     *= alpha;
                O[nt][2 * r + 1] *= alpha;
            }
        }

        // ---- O += P . V : P A-fragments from S C-fragments via quad shuffles
        int l0 = (lane & 28) | (tig >> 1);
        int l1 = l0 + 2;
        bool odd = (tig & 1);
#pragma unroll
        for (int kc = 0; kc < 8; kc++) {
            float s0 = __shfl_sync(0xffffffffu, S[kc][0], l0);
            float s1 = __shfl_sync(0xffffffffu, S[kc][1], l0);
            float s2 = __shfl_sync(0xffffffffu, S[kc][2], l0);
            float s3 = __shfl_sync(0xffffffffu, S[kc][3], l0);
            float t0 = __shfl_sync(0xffffffffu, S[kc][0], l1);
            float t1 = __shfl_sync(0xffffffffu, S[kc][1], l1);
            float t2 = __shfl_sync(0xffffffffu, S[kc][2], l1);
            float t3 = __shfl_sync(0xffffffffu, S[kc][3], l1);
            float a0 = to_tf32(odd ? s1 : s0);
            float a1 = to_tf32(odd ? s3 : s2);
            float a2 = to_tf32(odd ? t1 : t0);
            float a3 = to_tf32(odd ? t3 : t2);
            int k0 = kc * 8;
#pragma unroll
            for (int nt = 0; nt < 8; nt++) {
                float b0 = Vs[(k0 + tig)     * KLD + nt * 8 + g];
                float b1 = Vs[(k0 + tig + 4) * KLD + nt * 8 + g];
                mma_tf32_v(O[nt], a0, a1, a2, a3, b0, b1);
            }
        }
    }

    // ---- write out: g_x[b][t][h*64 + d]
    int b = bh / HH, h = bh % HH;
    float inv0 = 1.f / l_r[0], inv1 = 1.f / l_r[1];
    int t0 = qt * QTR + mb + g;
#pragma unroll
    for (int nt = 0; nt < 8; nt++) {
        int col = h * DHH + nt * 8 + 2 * tig;
        *(float2*)(g_x + (size_t)(b * TT + t0) * DD + col) =
            make_float2(O[nt][0] * inv0, O[nt][1] * inv0);
        *(float2*)(g_x + (size_t)(b * TT + t0 + 8) * DD + col) =
            make_float2(O[nt][2] * inv1, O[nt][3] * inv1);
    }
}

// =====================================================================
// Launch
// =====================================================================
extern "C" void kernel_launch(void* const* d_in, const int* in_sizes, int n_in,
                              void* d_out, int out_size)
{
    const float* x1    = (const float*)d_in[0];
    const float* x2    = (const float*)d_in[1];
    const float* Wqkv1 = (const float*)d_in[2];
    const float* bqkv1 = (const float*)d_in[3];
    const float* Wqkv2 = (const float*)d_in[4];
    const float* bqkv2 = (const float*)d_in[5];
    const float* Wout1 = (const float*)d_in[6];
    const float* bout1 = (const float*)d_in[7];
    const float* Wout2 = (const float*)d_in[8];
    const float* bout2 = (const float*)d_in[9];
    const float* gq1   = (const float*)d_in[10];
    const float* gk1   = (const float*)d_in[11];
    const float* gq2   = (const float*)d_in[12];
    const float* gk2   = (const float*)d_in[13];
    float* out = (float*)d_out;

    float* p_qkv = nullptr; float* p_x = nullptr;
    cudaGetSymbolAddress((void**)&p_qkv, g_qkv);
    cudaGetSymbolAddress((void**)&p_x, g_x);

    // QKV projections -> [B, T, 3D]
    sgemm_tf32<<<dim3(ND3 / 128, (BB * N1L) / 128), 256>>>(
        x1, Wqkv1, bqkv1, p_qkv, BB * N1L, ND3, DD,
        BB * N1L, 0, BB * N1L,
        N1L, 0, TT);
    sgemm_tf32<<<dim3(ND3 / 128, (BB * N2L) / 128), 256>>>(
        x2, Wqkv2, bqkv2, p_qkv, BB * N2L, ND3, DD,
        BB * N2L, 0, BB * N2L,
        N2L, N1L, TT);

    // RMSNorm + scatter to [B,H,T,64]
    rms_scatter_kernel<<<(BB * TT * HH * 32) / 256, 256>>>(gq1, gk1, gq2, gk2);

    // Attention: 70KB dynamic smem, 2 CTAs/SM
    int smem = (QTR * QLD + 2 * 64 * KLD) * (int)sizeof(float);  // 71680
    cudaFuncSetAttribute(attn_kernel, cudaFuncAttributeMaxDynamicSharedMemorySize, smem);
    attn_kernel<<<dim3(NQT, BB * HH), 256, smem>>>();

    // Output projections
    sgemm_tf32<<<dim3(DD / 128, (BB * N1L) / 128), 256>>>(
        p_x, Wout1, bout1, out, BB * N1L, DD, DD,
        N1L, 0, TT,
        BB * N1L, 0, BB * N1L);
    sgemm_tf32<<<dim3(DD / 128, (BB * N2L) / 128), 256>>>(
        p_x, Wout2, bout2, out + (size_t)BB * N1L * DD, BB * N2L, DD, DD,
        N2L, N1L, TT,
        BB * N2L, 0, BB * N2L);
}

// round 5
// speedup vs baseline: 1.9156x; 1.0430x over previous
#include <cuda_runtime.h>
#include <math.h>
#include <stdint.h>

// ---------------- problem constants ----------------
#define BB   2
#define N1L  2048
#define N2L  128
#define TT   2176          // N1 + N2
#define DD   1024
#define HH   16
#define DHH  64
#define ND3  3072          // 3*D
#define NKT  34            // T/64 kv tiles
#define QTR  128           // q rows per attn block
#define NQT  17            // T/128 q tiles

// ---------------- scratch (__device__ globals; no allocs allowed) ----------------
__device__ float g_qkv[BB * TT * ND3];        // [B, T, 3*D]
__device__ float g_q[BB * HH * TT * DHH];     // [B,H,T,64]  (1/8 scale folded)
__device__ float g_k[BB * HH * TT * DHH];
__device__ float g_v[BB * HH * TT * DHH];
__device__ float g_x[BB * TT * DD];           // attention output, heads merged

// ---------------- helpers ----------------
__device__ __forceinline__ float to_tf32(float x) {
    uint32_t u;
    asm("cvt.rna.tf32.f32 %0, %1;" : "=r"(u) : "f"(x));
    return __uint_as_float(u);
}

__device__ __forceinline__ void mma_tf32_v(float* c, const float a0, const float a1,
                                           const float a2, const float a3,
                                           const float b0, const float b1) {
    asm volatile(
        "mma.sync.aligned.m16n8k8.row.col.f32.tf32.tf32.f32 "
        "{%0,%1,%2,%3}, {%4,%5,%6,%7}, {%8,%9}, {%0,%1,%2,%3};"
        : "+f"(c[0]), "+f"(c[1]), "+f"(c[2]), "+f"(c[3])
        : "r"(__float_as_uint(a0)), "r"(__float_as_uint(a1)),
          "r"(__float_as_uint(a2)), "r"(__float_as_uint(a3)),
          "r"(__float_as_uint(b0)), "r"(__float_as_uint(b1)));
}

// =====================================================================
// tf32 tensor-core SGEMM (R1 layout) + double buffering. (unchanged R3)
// BM=128, BN=128, BK=16; 256 threads = 8 warps of 64x32 warp-tiles.
// C[remap_c(r)] = A[remap_a(r)] @ W + bias
// =====================================================================
#define ALD 20     // As row stride
#define BLD 136    // Bs row stride
__global__ __launch_bounds__(256) void sgemm_tf32(
    const float* __restrict__ A, const float* __restrict__ W,
    const float* __restrict__ bias, float* __restrict__ C,
    int M, int N, int K,
    int a_per, int a_base, int a_span,
    int c_per, int c_base, int c_span)
{
    __shared__ float As[2][128 * ALD];
    __shared__ float Bs[2][16 * BLD];

    int tid = threadIdx.x;
    int bm = blockIdx.y, bn = blockIdx.x;
    int warp = tid >> 5, lane = tid & 31;
    int g = lane >> 2, tig = lane & 3;
    int wm = (warp >> 2) * 64, wn = (warp & 3) * 32;

    int a_row[2], a_kq[2];
    const float* a_ptr[2];
#pragma unroll
    for (int i = 0; i < 2; i++) {
        int idx = tid + i * 256;
        a_row[i] = idx >> 2;
        a_kq[i]  = (idx & 3) * 4;
        int gr = bm * 128 + a_row[i];
        int arow = (gr / a_per) * a_span + a_base + (gr % a_per);
        a_ptr[i] = A + (size_t)arow * K + a_kq[i];
    }
    int b_kr[2], b_nq[2];
    const float* b_ptr[2];
#pragma unroll
    for (int i = 0; i < 2; i++) {
        int idx = tid + i * 256;
        b_kr[i] = idx >> 5;
        b_nq[i] = (idx & 31) * 4;
        b_ptr[i] = W + (size_t)b_kr[i] * N + bn * 128 + b_nq[i];
    }

    float acc[4][4][4];
#pragma unroll
    for (int mt = 0; mt < 4; mt++)
#pragma unroll
        for (int nt = 0; nt < 4; nt++)
#pragma unroll
            for (int r = 0; r < 4; r++) acc[mt][nt][r] = 0.f;

    int ntiles = K >> 4;

    float4 av[2], bv[2];
#pragma unroll
    for (int i = 0; i < 2; i++) {
        av[i] = *(const float4*)(a_ptr[i]);
        bv[i] = *(const float4*)(b_ptr[i]);
    }
#pragma unroll
    for (int i = 0; i < 2; i++) {
        float* as = &As[0][a_row[i] * ALD + a_kq[i]];
        as[0] = to_tf32(av[i].x); as[1] = to_tf32(av[i].y);
        as[2] = to_tf32(av[i].z); as[3] = to_tf32(av[i].w);
        float* bs = &Bs[0][b_kr[i] * BLD + b_nq[i]];
        bs[0] = to_tf32(bv[i].x); bs[1] = to_tf32(bv[i].y);
        bs[2] = to_tf32(bv[i].z); bs[3] = to_tf32(bv[i].w);
    }
    __syncthreads();

    for (int t = 0; t < ntiles; t++) {
        int cur = t & 1;
        if (t + 1 < ntiles) {
            int kk = (t + 1) * 16;
#pragma unroll
            for (int i = 0; i < 2; i++) {
                av[i] = *(const float4*)(a_ptr[i] + kk);
                bv[i] = *(const float4*)(b_ptr[i] + (size_t)kk * N);
            }
        }
#pragma unroll
        for (int ks = 0; ks < 16; ks += 8) {
            float afr[4][4], bfr[4][2];
#pragma unroll
            for (int mt = 0; mt < 4; mt++) {
                int rb = wm + mt * 16;
                afr[mt][0] = As[cur][(rb + g)     * ALD + ks + tig];
                afr[mt][1] = As[cur][(rb + g + 8) * ALD + ks + tig];
                afr[mt][2] = As[cur][(rb + g)     * ALD + ks + tig + 4];
                afr[mt][3] = As[cur][(rb + g + 8) * ALD + ks + tig + 4];
            }
#pragma unroll
            for (int nt = 0; nt < 4; nt++) {
                int nb = wn + nt * 8;
                bfr[nt][0] = Bs[cur][(ks + tig)     * BLD + nb + g];
                bfr[nt][1] = Bs[cur][(ks + tig + 4) * BLD + nb + g];
            }
#pragma unroll
            for (int mt = 0; mt < 4; mt++)
#pragma unroll
                for (int nt = 0; nt < 4; nt++)
                    mma_tf32_v(acc[mt][nt], afr[mt][0], afr[mt][1], afr[mt][2], afr[mt][3],
                               bfr[nt][0], bfr[nt][1]);
        }
        if (t + 1 < ntiles) {
            int nxt = cur ^ 1;
#pragma unroll
            for (int i = 0; i < 2; i++) {
                float* as = &As[nxt][a_row[i] * ALD + a_kq[i]];
                as[0] = to_tf32(av[i].x); as[1] = to_tf32(av[i].y);
                as[2] = to_tf32(av[i].z); as[3] = to_tf32(av[i].w);
                float* bs = &Bs[nxt][b_kr[i] * BLD + b_nq[i]];
                bs[0] = to_tf32(bv[i].x); bs[1] = to_tf32(bv[i].y);
                bs[2] = to_tf32(bv[i].z); bs[3] = to_tf32(bv[i].w);
            }
        }
        __syncthreads();
    }

#pragma unroll
    for (int mt = 0; mt < 4; mt++) {
        int gm0 = bm * 128 + wm + mt * 16 + g;
        int gm1 = gm0 + 8;
        int cr0 = (gm0 / c_per) * c_span + c_base + (gm0 % c_per);
        int cr1 = (gm1 / c_per) * c_span + c_base + (gm1 % c_per);
#pragma unroll
        for (int nt = 0; nt < 4; nt++) {
            int cn = bn * 128 + wn + nt * 8 + 2 * tig;
            float2 bi = *(const float2*)(bias + cn);
            *(float2*)(C + (size_t)cr0 * N + cn) =
                make_float2(acc[mt][nt][0] + bi.x, acc[mt][nt][1] + bi.y);
            *(float2*)(C + (size_t)cr1 * N + cn) =
                make_float2(acc[mt][nt][2] + bi.x, acc[mt][nt][3] + bi.y);
        }
    }
}

// =====================================================================
// RMSNorm(q,k) + scatter q/k/v from [B,T,3D] into [B,H,T,64]. (unchanged)
// =====================================================================
__global__ __launch_bounds__(256) void rms_scatter_kernel(
    const float* __restrict__ gq1, const float* __restrict__ gk1,
    const float* __restrict__ gq2, const float* __restrict__ gk2)
{
    int warp = (blockIdx.x * blockDim.x + threadIdx.x) >> 5;
    int lane = threadIdx.x & 31;
    if (warp >= BB * TT * HH) return;
    int h = warp % HH;
    int bt = warp / HH;
    int t = bt % TT;
    int b = bt / TT;

    const float* base = g_qkv + (size_t)(b * TT + t) * ND3;
    const float* gq = (t < N1L) ? gq1 : gq2;
    const float* gk = (t < N1L) ? gk1 : gk2;

    int d0 = lane * 2;
    float2 qv = *(const float2*)(base + h * DHH + d0);
    float2 kv = *(const float2*)(base + DD + h * DHH + d0);
    float2 vv = *(const float2*)(base + 2 * DD + h * DHH + d0);

    float ssq = qv.x * qv.x + qv.y * qv.y;
    float ssk = kv.x * kv.x + kv.y * kv.y;
#pragma unroll
    for (int off = 16; off > 0; off >>= 1) {
        ssq += __shfl_xor_sync(0xffffffffu, ssq, off);
        ssk += __shfl_xor_sync(0xffffffffu, ssk, off);
    }
    float rq = rsqrtf(ssq * (1.f / 64.f) + 1e-6f) * 0.125f;
    float rk = rsqrtf(ssk * (1.f / 64.f) + 1e-6f);

    float2 gqv = *(const float2*)(gq + d0);
    float2 gkv = *(const float2*)(gk + d0);

    int o = ((b * HH + h) * TT + t) * DHH + d0;
    *(float2*)(g_q + o) = make_float2(qv.x * rq * gqv.x, qv.y * rq * gqv.y);
    *(float2*)(g_k + o) = make_float2(kv.x * rk * gkv.x, kv.y * rk * gkv.y);
    *(float2*)(g_v + o) = vv;
}

// =====================================================================
// Flash attention, tf32 mma, m=32 per warp (2 m16 frags share b loads).
// grid = (17, B*H). 128 threads (4 warps), 128 q-rows/block, 64-kv tiles.
// Smem: Qs [128][68] + Ks [64][72] + Vs [64][72] = 71680 B -> 2 CTAs/SM.
// =====================================================================
#define QLD 68     // Qs row stride
#define KLD 72     // Ks/Vs row stride
__global__ __launch_bounds__(128, 2) void attn_kernel()
{
    extern __shared__ float sm[];
    float* Qs = sm;                     // [128][68]  (q, d)
    float* Ks = Qs + QTR * QLD;         // [64][72]   (d, kv)  transposed
    float* Vs = Ks + 64 * KLD;          // [64][72]   (kv, d)

    int qt = blockIdx.x;                // 0..16
    int bh = blockIdx.y;                // 0..31
    int tid = threadIdx.x;
    int warp = tid >> 5, lane = tid & 31;
    int g = lane >> 2, tig = lane & 3;
    int mb = warp * 32;                 // warp owns rows mb..mb+31 (2 frags)

    const float* Qg = g_q + (size_t)(bh * TT + qt * QTR) * DHH;
    const float* Kg = g_k + (size_t)bh * TT * DHH;
    const float* Vg = g_v + (size_t)bh * TT * DHH;

    // Load Q tile (tf32-rounded): 128x64 = 2048 float4, 128 threads -> 16 iters
#pragma unroll
    for (int i = 0; i < 16; i++) {
        int idx = tid + i * 128;
        int r = idx >> 4, dq = (idx & 15) * 4;
        float4 v = *(const float4*)(Qg + r * DHH + dq);
        float* qs = &Qs[r * QLD + dq];
        qs[0] = to_tf32(v.x); qs[1] = to_tf32(v.y);
        qs[2] = to_tf32(v.z); qs[3] = to_tf32(v.w);
    }

    float S[2][8][4], O[2][8][4];
    float m_r[2][2], l_r[2][2];
#pragma unroll
    for (int f = 0; f < 2; f++) {
#pragma unroll
        for (int nt = 0; nt < 8; nt++)
#pragma unroll
            for (int r = 0; r < 4; r++) O[f][nt][r] = 0.f;
        m_r[f][0] = m_r[f][1] = -1e30f;
        l_r[f][0] = l_r[f][1] = 0.f;
    }

    for (int kt = 0; kt < NKT; kt++) {
        __syncthreads();   // prev PV done with Ks/Vs; Q visible on iter 0
        const float* Kt = Kg + kt * 64 * DHH;
        const float* Vt = Vg + kt * 64 * DHH;
        // 64x64 each: 1024 float4 per array, 128 threads -> 8 iters
#pragma unroll
        for (int i = 0; i < 8; i++) {
            int idx = tid + i * 128;
            int r = idx >> 4, dq = (idx & 15) * 4;
            float4 kv4 = *(const float4*)(Kt + r * DHH + dq);
            Ks[(dq + 0) * KLD + r] = to_tf32(kv4.x);
            Ks[(dq + 1) * KLD + r] = to_tf32(kv4.y);
            Ks[(dq + 2) * KLD + r] = to_tf32(kv4.z);
            Ks[(dq + 3) * KLD + r] = to_tf32(kv4.w);
            float4 vv4 = *(const float4*)(Vt + r * DHH + dq);
            float* vs = &Vs[r * KLD + dq];
            vs[0] = to_tf32(vv4.x); vs[1] = to_tf32(vv4.y);
            vs[2] = to_tf32(vv4.z); vs[3] = to_tf32(vv4.w);
        }
        __syncthreads();

        // ---- S = Q . K^T  (warp: m32 x n64, k=64; b shared by both m-frags)
#pragma unroll
        for (int f = 0; f < 2; f++)
#pragma unroll
            for (int nt = 0; nt < 8; nt++)
#pragma unroll
                for (int r = 0; r < 4; r++) S[f][nt][r] = 0.f;
#pragma unroll
        for (int ks = 0; ks < 8; ks++) {
            int k0 = ks * 8;
            float a[2][4];
#pragma unroll
            for (int f = 0; f < 2; f++) {
                int rb = mb + f * 16;
                a[f][0] = Qs[(rb + g)     * QLD + k0 + tig];
                a[f][1] = Qs[(rb + g + 8) * QLD + k0 + tig];
                a[f][2] = Qs[(rb + g)     * QLD + k0 + tig + 4];
                a[f][3] = Qs[(rb + g + 8) * QLD + k0 + tig + 4];
            }
#pragma unroll
            for (int nt = 0; nt < 8; nt++) {
                float b0 = Ks[(k0 + tig)     * KLD + nt * 8 + g];
                float b1 = Ks[(k0 + tig + 4) * KLD + nt * 8 + g];
                mma_tf32_v(S[0][nt], a[0][0], a[0][1], a[0][2], a[0][3], b0, b1);
                mma_tf32_v(S[1][nt], a[1][0], a[1][1], a[1][2], a[1][3], b0, b1);
            }
        }

        float biasv = (qt < 16 && kt < 32 && (kt >> 2) > (qt >> 1)) ? 1.0f : 0.0f;

        // ---- online softmax per frag; p kept in S regs
#pragma unroll
        for (int f = 0; f < 2; f++) {
#pragma unroll
            for (int r = 0; r < 2; r++) {
                float mx = -1e30f;
#pragma unroll
                for (int nt = 0; nt < 8; nt++) {
                    S[f][nt][2 * r]     += biasv;
                    S[f][nt][2 * r + 1] += biasv;
                    mx = fmaxf(mx, fmaxf(S[f][nt][2 * r], S[f][nt][2 * r + 1]));
                }
                mx = fmaxf(mx, __shfl_xor_sync(0xffffffffu, mx, 1));
                mx = fmaxf(mx, __shfl_xor_sync(0xffffffffu, mx, 2));
                float mn = fmaxf(m_r[f][r], mx);
                float rs = 0.f;
#pragma unroll
                for (int nt = 0; nt < 8; nt++) {
                    float p0 = __expf(S[f][nt][2 * r]     - mn);
                    float p1 = __expf(S[f][nt][2 * r + 1] - mn);
                    S[f][nt][2 * r]     = p0;
                    S[f][nt][2 * r + 1] = p1;
                    rs += p0 + p1;
                }
                rs += __shfl_xor_sync(0xffffffffu, rs, 1);
                rs += __shfl_xor_sync(0xffffffffu, rs, 2);
                float alpha = __expf(m_r[f][r] - mn);
                l_r[f][r] = l_r[f][r] * alpha + rs;
                m_r[f][r] = mn;
#pragma unroll
                for (int nt = 0; nt < 8; nt++) {
                    O[f][nt][2 * r]     *= alpha;
                    O[f][nt][2 * r + 1] *= alpha;
                }
            }
        }

        // ---- O += P . V : P A-frags via quad shuffles; b shared by both frags
        int l0 = (lane & 28) | (tig >> 1);
        int l1 = l0 + 2;
        bool odd = (tig & 1);
#pragma unroll
        for (int kc = 0; kc < 8; kc++) {
            float a[2][4];
#pragma unroll
            for (int f = 0; f < 2; f++) {
                float s0 = __shfl_sync(0xffffffffu, S[f][kc][0], l0);
                float s1 = __shfl_sync(0xffffffffu, S[f][kc][1], l0);
                float s2 = __shfl_sync(0xffffffffu, S[f][kc][2], l0);
                float s3 = __shfl_sync(0xffffffffu, S[f][kc][3], l0);
                float t0 = __shfl_sync(0xffffffffu, S[f][kc][0], l1);
                float t1 = __shfl_sync(0xffffffffu, S[f][kc][1], l1);
                float t2 = __shfl_sync(0xffffffffu, S[f][kc][2], l1);
                float t3 = __shfl_sync(0xffffffffu, S[f][kc][3], l1);
                a[f][0] = to_tf32(odd ? s1 : s0);
                a[f][1] = to_tf32(odd ? s3 : s2);
                a[f][2] = to_tf32(odd ? t1 : t0);
                a[f][3] = to_tf32(odd ? t3 : t2);
            }
            int k0 = kc * 8;
#pragma unroll
            for (int nt = 0; nt < 8; nt++) {
                float b0 = Vs[(k0 + tig)     * KLD + nt * 8 + g];
                float b1 = Vs[(k0 + tig + 4) * KLD + nt * 8 + g];
                mma_tf32_v(O[0][nt], a[0][0], a[0][1], a[0][2], a[0][3], b0, b1);
                mma_tf32_v(O[1][nt], a[1][0], a[1][1], a[1][2], a[1][3], b0, b1);
            }
        }
    }

    // ---- write out: g_x[b][t][h*64 + d]
    int b = bh / HH, h = bh % HH;
#pragma unroll
    for (int f = 0; f < 2; f++) {
        float inv0 = 1.f / l_r[f][0], inv1 = 1.f / l_r[f][1];
        int t0 = qt * QTR + mb + f * 16 + g;
#pragma unroll
        for (int nt = 0; nt < 8; nt++) {
            int col = h * DHH + nt * 8 + 2 * tig;
            *(float2*)(g_x + (size_t)(b * TT + t0) * DD + col) =
                make_float2(O[f][nt][0] * inv0, O[f][nt][1] * inv0);
            *(float2*)(g_x + (size_t)(b * TT + t0 + 8) * DD + col) =
                make_float2(O[f][nt][2] * inv1, O[f][nt][3] * inv1);
        }
    }
}

// =====================================================================
// Launch
// =====================================================================
extern "C" void kernel_launch(void* const* d_in, const int* in_sizes, int n_in,
                              void* d_out, int out_size)
{
    const float* x1    = (const float*)d_in[0];
    const float* x2    = (const float*)d_in[1];
    const float* Wqkv1 = (const float*)d_in[2];
    const float* bqkv1 = (const float*)d_in[3];
    const float* Wqkv2 = (const float*)d_in[4];
    const float* bqkv2 = (const float*)d_in[5];
    const float* Wout1 = (const float*)d_in[6];
    const float* bout1 = (const float*)d_in[7];
    const float* Wout2 = (const float*)d_in[8];
    const float* bout2 = (const float*)d_in[9];
    const float* gq1   = (const float*)d_in[10];
    const float* gk1   = (const float*)d_in[11];
    const float* gq2   = (const float*)d_in[12];
    const float* gk2   = (const float*)d_in[13];
    float* out = (float*)d_out;

    float* p_qkv = nullptr; float* p_x = nullptr;
    cudaGetSymbolAddress((void**)&p_qkv, g_qkv);
    cudaGetSymbolAddress((void**)&p_x, g_x);

    // QKV projections -> [B, T, 3D]
    sgemm_tf32<<<dim3(ND3 / 128, (BB * N1L) / 128), 256>>>(
        x1, Wqkv1, bqkv1, p_qkv, BB * N1L, ND3, DD,
        BB * N1L, 0, BB * N1L,
        N1L, 0, TT);
    sgemm_tf32<<<dim3(ND3 / 128, (BB * N2L) / 128), 256>>>(
        x2, Wqkv2, bqkv2, p_qkv, BB * N2L, ND3, DD,
        BB * N2L, 0, BB * N2L,
        N2L, N1L, TT);

    // RMSNorm + scatter to [B,H,T,64]
    rms_scatter_kernel<<<(BB * TT * HH * 32) / 256, 256>>>(gq1, gk1, gq2, gk2);

    // Attention: 70KB dynamic smem, 128 threads, 2 CTAs/SM
    int smem = (QTR * QLD + 2 * 64 * KLD) * (int)sizeof(float);  // 71680
    cudaFuncSetAttribute(attn_kernel, cudaFuncAttributeMaxDynamicSharedMemorySize, smem);
    attn_kernel<<<dim3(NQT, BB * HH), 128, smem>>>();

    // Output projections
    sgemm_tf32<<<dim3(DD / 128, (BB * N1L) / 128), 256>>>(
        p_x, Wout1, bout1, out, BB * N1L, DD, DD,
        N1L, 0, TT,
        BB * N1L, 0, BB * N1L);
    sgemm_tf32<<<dim3(DD / 128, (BB * N2L) / 128), 256>>>(
        p_x, Wout2, bout2, out + (size_t)BB * N1L * DD, BB * N2L, DD, DD,
        N2L, N1L, TT,
        BB * N2L, 0, BB * N2L);
}

// round 7
// speedup vs baseline: 2.7262x; 1.4232x over previous
#include <cuda_runtime.h>
#include <math.h>
#include <stdint.h>

// ---------------- problem constants ----------------
#define BB   2
#define N1L  2048
#define N2L  128
#define TT   2176          // N1 + N2
#define DD   1024
#define HH   16
#define DHH  64
#define ND3  3072          // 3*D
#define NKT  34            // T/64 kv tiles
#define QTR  128           // q rows per attn block
#define NQT  17            // T/128 q tiles

// ---------------- scratch (__device__ globals; no allocs allowed) ----------------
__device__ float g_qkv[BB * TT * ND3];        // [B, T, 3*D]
__device__ float g_q[BB * HH * TT * DHH];     // [B,H,T,64]  (1/8 scale folded)
__device__ float g_k[BB * HH * TT * DHH];
__device__ float g_v[BB * HH * TT * DHH];
__device__ float g_x[BB * TT * DD];           // attention output, heads merged

// ---------------- helpers ----------------
__device__ __forceinline__ float to_tf32(float x) {
    uint32_t u;
    asm("cvt.rna.tf32.f32 %0, %1;" : "=r"(u) : "f"(x));
    return __uint_as_float(u);
}

__device__ __forceinline__ void mma_tf32_v(float* c, const float a0, const float a1,
                                           const float a2, const float a3,
                                           const float b0, const float b1) {
    asm volatile(
        "mma.sync.aligned.m16n8k8.row.col.f32.tf32.tf32.f32 "
        "{%0,%1,%2,%3}, {%4,%5,%6,%7}, {%8,%9}, {%0,%1,%2,%3};"
        : "+f"(c[0]), "+f"(c[1]), "+f"(c[2]), "+f"(c[3])
        : "r"(__float_as_uint(a0)), "r"(__float_as_uint(a1)),
          "r"(__float_as_uint(a2)), "r"(__float_as_uint(a3)),
          "r"(__float_as_uint(b0)), "r"(__float_as_uint(b1)));
}

// =====================================================================
// Dual-source tf32 SGEMM (R3 body): set chosen by blockIdx.y vs split.
// BM=128, BN=128, BK=16; 256 threads = 8 warps of 64x32 warp-tiles.
// =====================================================================
#define ALD 20     // As row stride
#define BLD 136    // Bs row stride
__global__ __launch_bounds__(256) void sgemm_tf32_dual(
    const float* __restrict__ A1, const float* __restrict__ W1,
    const float* __restrict__ bias1, float* __restrict__ C1,
    const float* __restrict__ A2, const float* __restrict__ W2,
    const float* __restrict__ bias2, float* __restrict__ C2,
    int N, int K, int split,
    int a_per1, int a_base1, int a_span1, int c_per1, int c_base1, int c_span1,
    int a_per2, int a_base2, int a_span2, int c_per2, int c_base2, int c_span2)
{
    __shared__ float As[2][128 * ALD];
    __shared__ float Bs[2][16 * BLD];

    bool s0 = (blockIdx.y < (unsigned)split);
    const float* A    = s0 ? A1 : A2;
    const float* W    = s0 ? W1 : W2;
    const float* bias = s0 ? bias1 : bias2;
    float* C          = s0 ? C1 : C2;
    int bm     = s0 ? blockIdx.y : blockIdx.y - split;
    int a_per  = s0 ? a_per1  : a_per2;
    int a_base = s0 ? a_base1 : a_base2;
    int a_span = s0 ? a_span1 : a_span2;
    int c_per  = s0 ? c_per1  : c_per2;
    int c_base = s0 ? c_base1 : c_base2;
    int c_span = s0 ? c_span1 : c_span2;

    int tid = threadIdx.x;
    int bn = blockIdx.x;
    int warp = tid >> 5, lane = tid & 31;
    int g = lane >> 2, tig = lane & 3;
    int wm = (warp >> 2) * 64, wn = (warp & 3) * 32;

    int a_row[2], a_kq[2];
    const float* a_ptr[2];
#pragma unroll
    for (int i = 0; i < 2; i++) {
        int idx = tid + i * 256;
        a_row[i] = idx >> 2;
        a_kq[i]  = (idx & 3) * 4;
        int gr = bm * 128 + a_row[i];
        int arow = (gr / a_per) * a_span + a_base + (gr % a_per);
        a_ptr[i] = A + (size_t)arow * K + a_kq[i];
    }
    int b_kr[2], b_nq[2];
    const float* b_ptr[2];
#pragma unroll
    for (int i = 0; i < 2; i++) {
        int idx = tid + i * 256;
        b_kr[i] = idx >> 5;
        b_nq[i] = (idx & 31) * 4;
        b_ptr[i] = W + (size_t)b_kr[i] * N + bn * 128 + b_nq[i];
    }

    float acc[4][4][4];
#pragma unroll
    for (int mt = 0; mt < 4; mt++)
#pragma unroll
        for (int nt = 0; nt < 4; nt++)
#pragma unroll
            for (int r = 0; r < 4; r++) acc[mt][nt][r] = 0.f;

    int ntiles = K >> 4;

    float4 av[2], bv[2];
#pragma unroll
    for (int i = 0; i < 2; i++) {
        av[i] = *(const float4*)(a_ptr[i]);
        bv[i] = *(const float4*)(b_ptr[i]);
    }
#pragma unroll
    for (int i = 0; i < 2; i++) {
        float* as = &As[0][a_row[i] * ALD + a_kq[i]];
        as[0] = to_tf32(av[i].x); as[1] = to_tf32(av[i].y);
        as[2] = to_tf32(av[i].z); as[3] = to_tf32(av[i].w);
        float* bs = &Bs[0][b_kr[i] * BLD + b_nq[i]];
        bs[0] = to_tf32(bv[i].x); bs[1] = to_tf32(bv[i].y);
        bs[2] = to_tf32(bv[i].z); bs[3] = to_tf32(bv[i].w);
    }
    __syncthreads();

    for (int t = 0; t < ntiles; t++) {
        int cur = t & 1;
        if (t + 1 < ntiles) {
            int kk = (t + 1) * 16;
#pragma unroll
            for (int i = 0; i < 2; i++) {
                av[i] = *(const float4*)(a_ptr[i] + kk);
                bv[i] = *(const float4*)(b_ptr[i] + (size_t)kk * N);
            }
        }
#pragma unroll
        for (int ks = 0; ks < 16; ks += 8) {
            float afr[4][4], bfr[4][2];
#pragma unroll
            for (int mt = 0; mt < 4; mt++) {
                int rb = wm + mt * 16;
                afr[mt][0] = As[cur][(rb + g)     * ALD + ks + tig];
                afr[mt][1] = As[cur][(rb + g + 8) * ALD + ks + tig];
                afr[mt][2] = As[cur][(rb + g)     * ALD + ks + tig + 4];
                afr[mt][3] = As[cur][(rb + g + 8) * ALD + ks + tig + 4];
            }
#pragma unroll
            for (int nt = 0; nt < 4; nt++) {
                int nb = wn + nt * 8;
                bfr[nt][0] = Bs[cur][(ks + tig)     * BLD + nb + g];
                bfr[nt][1] = Bs[cur][(ks + tig + 4) * BLD + nb + g];
            }
#pragma unroll
            for (int mt = 0; mt < 4; mt++)
#pragma unroll
                for (int nt = 0; nt < 4; nt++)
                    mma_tf32_v(acc[mt][nt], afr[mt][0], afr[mt][1], afr[mt][2], afr[mt][3],
                               bfr[nt][0], bfr[nt][1]);
        }
        if (t + 1 < ntiles) {
            int nxt = cur ^ 1;
#pragma unroll
            for (int i = 0; i < 2; i++) {
                float* as = &As[nxt][a_row[i] * ALD + a_kq[i]];
                as[0] = to_tf32(av[i].x); as[1] = to_tf32(av[i].y);
                as[2] = to_tf32(av[i].z); as[3] = to_tf32(av[i].w);
                float* bs = &Bs[nxt][b_kr[i] * BLD + b_nq[i]];
                bs[0] = to_tf32(bv[i].x); bs[1] = to_tf32(bv[i].y);
                bs[2] = to_tf32(bv[i].z); bs[3] = to_tf32(bv[i].w);
            }
        }
        __syncthreads();
    }

#pragma unroll
    for (int mt = 0; mt < 4; mt++) {
        int gm0 = bm * 128 + wm + mt * 16 + g;
        int gm1 = gm0 + 8;
        int cr0 = (gm0 / c_per) * c_span + c_base + (gm0 % c_per);
        int cr1 = (gm1 / c_per) * c_span + c_base + (gm1 % c_per);
#pragma unroll
        for (int nt = 0; nt < 4; nt++) {
            int cn = bn * 128 + wn + nt * 8 + 2 * tig;
            float2 bi = *(const float2*)(bias + cn);
            *(float2*)(C + (size_t)cr0 * N + cn) =
                make_float2(acc[mt][nt][0] + bi.x, acc[mt][nt][1] + bi.y);
            *(float2*)(C + (size_t)cr1 * N + cn) =
                make_float2(acc[mt][nt][2] + bi.x, acc[mt][nt][3] + bi.y);
        }
    }
}

// =====================================================================
// RMSNorm(q,k) + scatter q/k/v from [B,T,3D] into [B,H,T,64]. (unchanged)
// =====================================================================
__global__ __launch_bounds__(256) void rms_scatter_kernel(
    const float* __restrict__ gq1, const float* __restrict__ gk1,
    const float* __restrict__ gq2, const float* __restrict__ gk2)
{
    int warp = (blockIdx.x * blockDim.x + threadIdx.x) >> 5;
    int lane = threadIdx.x & 31;
    if (warp >= BB * TT * HH) return;
    int h = warp % HH;
    int bt = warp / HH;
    int t = bt % TT;
    int b = bt / TT;

    const float* base = g_qkv + (size_t)(b * TT + t) * ND3;
    const float* gq = (t < N1L) ? gq1 : gq2;
    const float* gk = (t < N1L) ? gk1 : gk2;

    int d0 = lane * 2;
    float2 qv = *(const float2*)(base + h * DHH + d0);
    float2 kv = *(const float2*)(base + DD + h * DHH + d0);
    float2 vv = *(const float2*)(base + 2 * DD + h * DHH + d0);

    float ssq = qv.x * qv.x + qv.y * qv.y;
    float ssk = kv.x * kv.x + kv.y * kv.y;
#pragma unroll
    for (int off = 16; off > 0; off >>= 1) {
        ssq += __shfl_xor_sync(0xffffffffu, ssq, off);
        ssk += __shfl_xor_sync(0xffffffffu, ssk, off);
    }
    float rq = rsqrtf(ssq * (1.f / 64.f) + 1e-6f) * 0.125f;
    float rk = rsqrtf(ssk * (1.f / 64.f) + 1e-6f);

    float2 gqv = *(const float2*)(gq + d0);
    float2 gkv = *(const float2*)(gk + d0);

    int o = ((b * HH + h) * TT + t) * DHH + d0;
    *(float2*)(g_q + o) = make_float2(qv.x * rq * gqv.x, qv.y * rq * gqv.y);
    *(float2*)(g_k + o) = make_float2(kv.x * rk * gkv.x, kv.y * rk * gkv.y);
    *(float2*)(g_v + o) = vv;
}

// =====================================================================
// Flash attention, tf32 mma, pair-packed Q/K smem (LDS.64 fragments),
// zero-shuffle P->A via V-row interleave permutation.
// grid = (17, B*H). 128 threads (4 warps), m=32/warp, 64-kv tiles.
// Smem: Qs2 8208 + Ks2 4112 + Vs 4352 floats = 66688 B -> 2 CTAs/SM.
// =====================================================================
// Qs2: [kc][row(128)][t(4)] float2 {k=8kc+t, k=8kc+t+4}, kc stride 513 f2
// Ks2: [kc][n(64)][t(4)]    float2 (same packing),       kc stride 257 f2
// Vs : [kv(64)][d] natural, row stride 68
#define QS2_KC 1026   // floats per kc chunk (513 float2)
#define KS2_KC 514    // floats per kc chunk (257 float2)
#define VLD    68
#define KS2_OFF (8 * QS2_KC)            // 8208
#define VS_OFF  (KS2_OFF + 8 * KS2_KC)  // 12320
#define ATTN_SMEM ((VS_OFF + 64 * VLD) * 4)   // 66688 bytes
__global__ __launch_bounds__(128, 2) void attn_kernel()
{
    extern __shared__ float sm[];
    float* Qs2 = sm;
    float* Ks2 = sm + KS2_OFF;
    float* Vs  = sm + VS_OFF;

    int qt = blockIdx.x;                // 0..16
    int bh = blockIdx.y;                // 0..31
    int tid = threadIdx.x;
    int warp = tid >> 5, lane = tid & 31;
    int g = lane >> 2, tig = lane & 3;
    int mb = warp * 32;                 // warp owns rows mb..mb+31 (2 frags)

    const float* Qg = g_q + (size_t)(bh * TT + qt * QTR) * DHH;
    const float* Kg = g_k + (size_t)bh * TT * DHH;
    const float* Vg = g_v + (size_t)bh * TT * DHH;

    // ---- pack Q: (r, d) -> Qs2[kc=d>>3][r][t=d&3] slot=(d>>2)&1
#pragma unroll
    for (int i = 0; i < 16; i++) {
        int idx = tid + i * 128;
        int r = idx >> 4, dq = (idx & 15) * 4;
        float4 v = *(const float4*)(Qg + r * DHH + dq);
        int kc = dq >> 3, slot = (dq >> 2) & 1;
        float* s = &Qs2[kc * QS2_KC + r * 8 + slot];
        s[0] = to_tf32(v.x); s[2] = to_tf32(v.y);
        s[4] = to_tf32(v.z); s[6] = to_tf32(v.w);
    }

    float S[2][8][4], O[2][8][4];
    float m_r[2][2], l_r[2][2];
#pragma unroll
    for (int f = 0; f < 2; f++) {
#pragma unroll
        for (int nt = 0; nt < 8; nt++)
#pragma unroll
            for (int r = 0; r < 4; r++) O[f][nt][r] = 0.f;
        m_r[f][0] = m_r[f][1] = -1e30f;
        l_r[f][0] = l_r[f][1] = 0.f;
    }

    for (int kt = 0; kt < NKT; kt++) {
        __syncthreads();   // prev compute done with Ks2/Vs; Qs2 visible iter 0
        const float* Kt = Kg + kt * 64 * DHH;
        const float* Vt = Vg + kt * 64 * DHH;
#pragma unroll
        for (int i = 0; i < 8; i++) {
            int idx = tid + i * 128;
            int r = idx >> 4, dq = (idx & 15) * 4;
            float4 kv4 = *(const float4*)(Kt + r * DHH + dq);
            int kc = dq >> 3, slot = (dq >> 2) & 1;
            float* s = &Ks2[kc * KS2_KC + r * 8 + slot];
            s[0] = to_tf32(kv4.x); s[2] = to_tf32(kv4.y);
            s[4] = to_tf32(kv4.z); s[6] = to_tf32(kv4.w);
            float4 vv4 = *(const float4*)(Vt + r * DHH + dq);
            *(float4*)&Vs[r * VLD + dq] = make_float4(
                to_tf32(vv4.x), to_tf32(vv4.y), to_tf32(vv4.z), to_tf32(vv4.w));
        }
        __syncthreads();

        // ---- S = Q . K^T  (warp: m32 x n64, k=64)
#pragma unroll
        for (int f = 0; f < 2; f++)
#pragma unroll
            for (int nt = 0; nt < 8; nt++)
#pragma unroll
                for (int r = 0; r < 4; r++) S[f][nt][r] = 0.f;
#pragma unroll
        for (int ks = 0; ks < 8; ks++) {
            const float* qb = &Qs2[ks * QS2_KC];
            const float* kb = &Ks2[ks * KS2_KC];
            float2 qA0 = *(const float2*)&qb[(mb + g)      * 8 + 2 * tig];
            float2 qA1 = *(const float2*)&qb[(mb + g + 8)  * 8 + 2 * tig];
            float2 qB0 = *(const float2*)&qb[(mb + g + 16) * 8 + 2 * tig];
            float2 qB1 = *(const float2*)&qb[(mb + g + 24) * 8 + 2 * tig];
#pragma unroll
            for (int nt = 0; nt < 8; nt++) {
                float2 b = *(const float2*)&kb[(nt * 8 + g) * 8 + 2 * tig];
                mma_tf32_v(S[0][nt], qA0.x, qA1.x, qA0.y, qA1.y, b.x, b.y);
                mma_tf32_v(S[1][nt], qB0.x, qB1.x, qB0.y, qB1.y, b.x, b.y);
            }
        }

        float biasv = (qt < 16 && kt < 32 && (kt >> 2) > (qt >> 1)) ? 1.0f : 0.0f;

        // ---- online softmax per frag; p kept in S regs
#pragma unroll
        for (int f = 0; f < 2; f++) {
#pragma unroll
            for (int r = 0; r < 2; r++) {
                float mx = -1e30f;
#pragma unroll
                for (int nt = 0; nt < 8; nt++) {
                    S[f][nt][2 * r]     += biasv;
                    S[f][nt][2 * r + 1] += biasv;
                    mx = fmaxf(mx, fmaxf(S[f][nt][2 * r], S[f][nt][2 * r + 1]));
                }
                mx = fmaxf(mx, __shfl_xor_sync(0xffffffffu, mx, 1));
                mx = fmaxf(mx, __shfl_xor_sync(0xffffffffu, mx, 2));
                float mn = fmaxf(m_r[f][r], mx);
                float rs = 0.f;
#pragma unroll
                for (int nt = 0; nt < 8; nt++) {
                    float p0 = __expf(S[f][nt][2 * r]     - mn);
                    float p1 = __expf(S[f][nt][2 * r + 1] - mn);
                    S[f][nt][2 * r]     = p0;
                    S[f][nt][2 * r + 1] = p1;
                    rs += p0 + p1;
                }
                rs += __shfl_xor_sync(0xffffffffu, rs, 1);
                rs += __shfl_xor_sync(0xffffffffu, rs, 2);
                float alpha = __expf(m_r[f][r] - mn);
                l_r[f][r] = l_r[f][r] * alpha + rs;
                m_r[f][r] = mn;
#pragma unroll
                for (int nt = 0; nt < 8; nt++) {
                    O[f][nt][2 * r]     *= alpha;
                    O[f][nt][2 * r + 1] *= alpha;
                }
            }
        }

        // ---- O += P . V, zero-shuffle:
        // mma physical k slot p<4 -> kv = k0+2p ; p>=4 -> kv = k0+2(p-4)+1.
        // A-frag regs = (c0, c2, c1, c3) of the S C-fragment; V rows 2t / 2t+1.
#pragma unroll
        for (int kc = 0; kc < 8; kc++) {
            int r0 = (kc * 8 + 2 * tig) * VLD;
            int r1 = r0 + VLD;
            float a00 = to_tf32(S[0][kc][0]);
            float a01 = to_tf32(S[0][kc][2]);
            float a02 = to_tf32(S[0][kc][1]);
            float a03 = to_tf32(S[0][kc][3]);
            float a10 = to_tf32(S[1][kc][0]);
            float a11 = to_tf32(S[1][kc][2]);
            float a12 = to_tf32(S[1][kc][1]);
            float a13 = to_tf32(S[1][kc][3]);
#pragma unroll
            for (int nt = 0; nt < 8; nt++) {
                float b0 = Vs[r0 + nt * 8 + g];
                float b1 = Vs[r1 + nt * 8 + g];
                mma_tf32_v(O[0][nt], a00, a01, a02, a03, b0, b1);
                mma_tf32_v(O[1][nt], a10, a11, a12, a13, b0, b1);
            }
        }
    }

    // ---- write out: g_x[b][t][h*64 + d]
    int b = bh / HH, h = bh % HH;
#pragma unroll
    for (int f = 0; f < 2; f++) {
        float inv0 = 1.f / l_r[f][0], inv1 = 1.f / l_r[f][1];
        int t0 = qt * QTR + mb + f * 16 + g;
#pragma unroll
        for (int nt = 0; nt < 8; nt++) {
            int col = h * DHH + nt * 8 + 2 * tig;
            *(float2*)(g_x + (size_t)(b * TT + t0) * DD + col) =
                make_float2(O[f][nt][0] * inv0, O[f][nt][1] * inv0);
            *(float2*)(g_x + (size_t)(b * TT + t0 + 8) * DD + col) =
                make_float2(O[f][nt][2] * inv1, O[f][nt][3] * inv1);
        }
    }
}

// =====================================================================
// Launch
// =====================================================================
extern "C" void kernel_launch(void* const* d_in, const int* in_sizes, int n_in,
                              void* d_out, int out_size)
{
    const float* x1    = (const float*)d_in[0];
    const float* x2    = (const float*)d_in[1];
    const float* Wqkv1 = (const float*)d_in[2];
    const float* bqkv1 = (const float*)d_in[3];
    const float* Wqkv2 = (const float*)d_in[4];
    const float* bqkv2 = (const float*)d_in[5];
    const float* Wout1 = (const float*)d_in[6];
    const float* bout1 = (const float*)d_in[7];
    const float* Wout2 = (const float*)d_in[8];
    const float* bout2 = (const float*)d_in[9];
    const float* gq1   = (const float*)d_in[10];
    const float* gk1   = (const float*)d_in[11];
    const float* gq2   = (const float*)d_in[12];
    const float* gk2   = (const float*)d_in[13];
    float* out = (float*)d_out;

    float* p_qkv = nullptr; float* p_x = nullptr;
    cudaGetSymbolAddress((void**)&p_qkv, g_qkv);
    cudaGetSymbolAddress((void**)&p_x, g_x);

    // QKV projections -> [B, T, 3D]  (x1: 32 tiles, x2: 2 tiles, merged)
    sgemm_tf32_dual<<<dim3(ND3 / 128, 34), 256>>>(
        x1, Wqkv1, bqkv1, p_qkv,
        x2, Wqkv2, bqkv2, p_qkv,
        ND3, DD, 32,
        BB * N1L, 0, BB * N1L,  N1L, 0, TT,      // set1: A identity, C rows b*T+n
        BB * N2L, 0, BB * N2L,  N2L, N1L, TT);   // set2: A identity, C rows b*T+2048+n

    // RMSNorm + scatter to [B,H,T,64]
    rms_scatter_kernel<<<(BB * TT * HH * 32) / 256, 256>>>(gq1, gk1, gq2, gk2);

    // Attention
    cudaFuncSetAttribute(attn_kernel, cudaFuncAttributeMaxDynamicSharedMemorySize, ATTN_SMEM);
    attn_kernel<<<dim3(NQT, BB * HH), 128, ATTN_SMEM>>>();

    // Output projections (out1: 32 tiles, out2: 2 tiles, merged)
    sgemm_tf32_dual<<<dim3(DD / 128, 34), 256>>>(
        p_x, Wout1, bout1, out,
        p_x, Wout2, bout2, out + (size_t)BB * N1L * DD,
        DD, DD, 32,
        N1L, 0, TT,        BB * N1L, 0, BB * N1L,   // set1: A rows b*T+n, C identity
        N2L, N1L, TT,      BB * N2L, 0, BB * N2L);  // set2: A rows b*T+2048+n, C identity
}

// round 9
// speedup vs baseline: 2.8469x; 1.0443x over previous
#include <cuda_runtime.h>
#include <math.h>
#include <stdint.h>

// ---------------- problem constants ----------------
#define BB   2
#define N1L  2048
#define N2L  128
#define TT   2176          // N1 + N2
#define DD   1024
#define HH   16
#define DHH  64
#define ND3  3072          // 3*D
#define NKT  34            // T/64 kv tiles
#define QTR  128           // q rows per attn block
#define NQT  17            // T/128 q tiles

// ---------------- scratch (__device__ globals; no allocs allowed) ----------------
__device__ float g_qkv[BB * TT * ND3];            // [B, T, 3*D]
// Packed, tf32-pre-rounded tiles for attention:
// Qp: [bh][qt(17)][kc(8)][r(128)][8]   elem (r,k): off = r*8 + 2*(k&3) + (k>>2)
// Kp: [bh][kt(34)][kc(8)][r(64)][8]    same packing per 64-row tile
// Vp: [bh][kt(34)][r(64)][68]          natural, padded stride 68
__device__ float g_qp[BB * HH * NQT * 8 * 128 * 8];
__device__ float g_kp[BB * HH * NKT * 8 * 64 * 8];
__device__ float g_vp[BB * HH * NKT * 64 * 68];
__device__ float g_x[BB * TT * DD];               // attention output, heads merged

// ---------------- helpers ----------------
__device__ __forceinline__ float to_tf32(float x) {
    uint32_t u;
    asm("cvt.rna.tf32.f32 %0, %1;" : "=r"(u) : "f"(x));
    return __uint_as_float(u);
}

__device__ __forceinline__ void mma_tf32_v(float* c, const float a0, const float a1,
                                           const float a2, const float a3,
                                           const float b0, const float b1) {
    asm volatile(
        "mma.sync.aligned.m16n8k8.row.col.f32.tf32.tf32.f32 "
        "{%0,%1,%2,%3}, {%4,%5,%6,%7}, {%8,%9}, {%0,%1,%2,%3};"
        : "+f"(c[0]), "+f"(c[1]), "+f"(c[2]), "+f"(c[3])
        : "r"(__float_as_uint(a0)), "r"(__float_as_uint(a1)),
          "r"(__float_as_uint(a2)), "r"(__float_as_uint(a3)),
          "r"(__float_as_uint(b0)), "r"(__float_as_uint(b1)));
}

__device__ __forceinline__ void cp16(uint32_t smem_dst, const void* gsrc) {
    asm volatile("cp.async.cg.shared.global [%0], [%1], 16;\n"
                 :: "r"(smem_dst), "l"(gsrc));
}
#define CP_COMMIT() asm volatile("cp.async.commit_group;\n" ::: "memory")
#define CP_WAIT1()  asm volatile("cp.async.wait_group 1;\n" ::: "memory")

// =====================================================================
// Dual-source tf32 SGEMM (unchanged from R5/R6 winner).
// =====================================================================
#define ALD 20
#define BLD 136
__global__ __launch_bounds__(256) void sgemm_tf32_dual(
    const float* __restrict__ A1, const float* __restrict__ W1,
    const float* __restrict__ bias1, float* __restrict__ C1,
    const float* __restrict__ A2, const float* __restrict__ W2,
    const float* __restrict__ bias2, float* __restrict__ C2,
    int N, int K, int split,
    int a_per1, int a_base1, int a_span1, int c_per1, int c_base1, int c_span1,
    int a_per2, int a_base2, int a_span2, int c_per2, int c_base2, int c_span2)
{
    __shared__ float As[2][128 * ALD];
    __shared__ float Bs[2][16 * BLD];

    bool s0 = (blockIdx.y < (unsigned)split);
    const float* A    = s0 ? A1 : A2;
    const float* W    = s0 ? W1 : W2;
    const float* bias = s0 ? bias1 : bias2;
    float* C          = s0 ? C1 : C2;
    int bm     = s0 ? blockIdx.y : blockIdx.y - split;
    int a_per  = s0 ? a_per1  : a_per2;
    int a_base = s0 ? a_base1 : a_base2;
    int a_span = s0 ? a_span1 : a_span2;
    int c_per  = s0 ? c_per1  : c_per2;
    int c_base = s0 ? c_base1 : c_base2;
    int c_span = s0 ? c_span1 : c_span2;

    int tid = threadIdx.x;
    int bn = blockIdx.x;
    int warp = tid >> 5, lane = tid & 31;
    int g = lane >> 2, tig = lane & 3;
    int wm = (warp >> 2) * 64, wn = (warp & 3) * 32;

    int a_row[2], a_kq[2];
    const float* a_ptr[2];
#pragma unroll
    for (int i = 0; i < 2; i++) {
        int idx = tid + i * 256;
        a_row[i] = idx >> 2;
        a_kq[i]  = (idx & 3) * 4;
        int gr = bm * 128 + a_row[i];
        int arow = (gr / a_per) * a_span + a_base + (gr % a_per);
        a_ptr[i] = A + (size_t)arow * K + a_kq[i];
    }
    int b_kr[2], b_nq[2];
    const float* b_ptr[2];
#pragma unroll
    for (int i = 0; i < 2; i++) {
        int idx = tid + i * 256;
        b_kr[i] = idx >> 5;
        b_nq[i] = (idx & 31) * 4;
        b_ptr[i] = W + (size_t)b_kr[i] * N + bn * 128 + b_nq[i];
    }

    float acc[4][4][4];
#pragma unroll
    for (int mt = 0; mt < 4; mt++)
#pragma unroll
        for (int nt = 0; nt < 4; nt++)
#pragma unroll
            for (int r = 0; r < 4; r++) acc[mt][nt][r] = 0.f;

    int ntiles = K >> 4;

    float4 av[2], bv[2];
#pragma unroll
    for (int i = 0; i < 2; i++) {
        av[i] = *(const float4*)(a_ptr[i]);
        bv[i] = *(const float4*)(b_ptr[i]);
    }
#pragma unroll
    for (int i = 0; i < 2; i++) {
        float* as = &As[0][a_row[i] * ALD + a_kq[i]];
        as[0] = to_tf32(av[i].x); as[1] = to_tf32(av[i].y);
        as[2] = to_tf32(av[i].z); as[3] = to_tf32(av[i].w);
        float* bs = &Bs[0][b_kr[i] * BLD + b_nq[i]];
        bs[0] = to_tf32(bv[i].x); bs[1] = to_tf32(bv[i].y);
        bs[2] = to_tf32(bv[i].z); bs[3] = to_tf32(bv[i].w);
    }
    __syncthreads();

    for (int t = 0; t < ntiles; t++) {
        int cur = t & 1;
        if (t + 1 < ntiles) {
            int kk = (t + 1) * 16;
#pragma unroll
            for (int i = 0; i < 2; i++) {
                av[i] = *(const float4*)(a_ptr[i] + kk);
                bv[i] = *(const float4*)(b_ptr[i] + (size_t)kk * N);
            }
        }
#pragma unroll
        for (int ks = 0; ks < 16; ks += 8) {
            float afr[4][4], bfr[4][2];
#pragma unroll
            for (int mt = 0; mt < 4; mt++) {
                int rb = wm + mt * 16;
                afr[mt][0] = As[cur][(rb + g)     * ALD + ks + tig];
                afr[mt][1] = As[cur][(rb + g + 8) * ALD + ks + tig];
                afr[mt][2] = As[cur][(rb + g)     * ALD + ks + tig + 4];
                afr[mt][3] = As[cur][(rb + g + 8) * ALD + ks + tig + 4];
            }
#pragma unroll
            for (int nt = 0; nt < 4; nt++) {
                int nb = wn + nt * 8;
                bfr[nt][0] = Bs[cur][(ks + tig)     * BLD + nb + g];
                bfr[nt][1] = Bs[cur][(ks + tig + 4) * BLD + nb + g];
            }
#pragma unroll
            for (int mt = 0; mt < 4; mt++)
#pragma unroll
                for (int nt = 0; nt < 4; nt++)
                    mma_tf32_v(acc[mt][nt], afr[mt][0], afr[mt][1], afr[mt][2], afr[mt][3],
                               bfr[nt][0], bfr[nt][1]);
        }
        if (t + 1 < ntiles) {
            int nxt = cur ^ 1;
#pragma unroll
            for (int i = 0; i < 2; i++) {
                float* as = &As[nxt][a_row[i] * ALD + a_kq[i]];
                as[0] = to_tf32(av[i].x); as[1] = to_tf32(av[i].y);
                as[2] = to_tf32(av[i].z); as[3] = to_tf32(av[i].w);
                float* bs = &Bs[nxt][b_kr[i] * BLD + b_nq[i]];
                bs[0] = to_tf32(bv[i].x); bs[1] = to_tf32(bv[i].y);
                bs[2] = to_tf32(bv[i].z); bs[3] = to_tf32(bv[i].w);
            }
        }
        __syncthreads();
    }

#pragma unroll
    for (int mt = 0; mt < 4; mt++) {
        int gm0 = bm * 128 + wm + mt * 16 + g;
        int gm1 = gm0 + 8;
        int cr0 = (gm0 / c_per) * c_span + c_base + (gm0 % c_per);
        int cr1 = (gm1 / c_per) * c_span + c_base + (gm1 % c_per);
#pragma unroll
        for (int nt = 0; nt < 4; nt++) {
            int cn = bn * 128 + wn + nt * 8 + 2 * tig;
            float2 bi = *(const float2*)(bias + cn);
            *(float2*)(C + (size_t)cr0 * N + cn) =
                make_float2(acc[mt][nt][0] + bi.x, acc[mt][nt][1] + bi.y);
            *(float2*)(C + (size_t)cr1 * N + cn) =
                make_float2(acc[mt][nt][2] + bi.x, acc[mt][nt][3] + bi.y);
        }
    }
}

// =====================================================================
// RMSNorm(q,k) + scatter into packed tf32 tile layouts.
// One warp per (b,t,h); lane covers d0=2*lane, d0+1.
// =====================================================================
__global__ __launch_bounds__(256) void rms_scatter_kernel(
    const float* __restrict__ gq1, const float* __restrict__ gk1,
    const float* __restrict__ gq2, const float* __restrict__ gk2)
{
    int warp = (blockIdx.x * blockDim.x + threadIdx.x) >> 5;
    int lane = threadIdx.x & 31;
    if (warp >= BB * TT * HH) return;
    int h = warp % HH;
    int bt = warp / HH;
    int t = bt % TT;
    int b = bt / TT;
    int bh = b * HH + h;

    const float* base = g_qkv + (size_t)(b * TT + t) * ND3;
    const float* gq = (t < N1L) ? gq1 : gq2;
    const float* gk = (t < N1L) ? gk1 : gk2;

    int d0 = lane * 2;
    float2 qv = *(const float2*)(base + h * DHH + d0);
    float2 kv = *(const float2*)(base + DD + h * DHH + d0);
    float2 vv = *(const float2*)(base + 2 * DD + h * DHH + d0);

    float ssq = qv.x * qv.x + qv.y * qv.y;
    float ssk = kv.x * kv.x + kv.y * kv.y;
#pragma unroll
    for (int off = 16; off > 0; off >>= 1) {
        ssq += __shfl_xor_sync(0xffffffffu, ssq, off);
        ssk += __shfl_xor_sync(0xffffffffu, ssk, off);
    }
    float rq = rsqrtf(ssq * (1.f / 64.f) + 1e-6f) * 0.125f;
    float rk = rsqrtf(ssk * (1.f / 64.f) + 1e-6f);

    float2 gqv = *(const float2*)(gq + d0);
    float2 gkv = *(const float2*)(gk + d0);

    float q0 = to_tf32(qv.x * rq * gqv.x), q1 = to_tf32(qv.y * rq * gqv.y);
    float k0 = to_tf32(kv.x * rk * gkv.x), k1 = to_tf32(kv.y * rk * gkv.y);

    // packed offsets: elem k within kc chunk -> 2*(k&3) + (k>>2)
    int kc = d0 >> 3;
    int e0 = d0 & 7, e1 = e0 + 1;
    int w0 = 2 * (e0 & 3) + (e0 >> 2);
    int w1 = 2 * (e1 & 3) + (e1 >> 2);

    // Q packed: [bh][qt][kc][r(128)][8]
    {
        int qt = t >> 7, r = t & 127;
        float* dst = g_qp + ((((size_t)bh * NQT + qt) * 8 + kc) * 128 + r) * 8;
        dst[w0] = q0; dst[w1] = q1;
    }
    // K packed: [bh][kt][kc][r(64)][8]
    {
        int kt = t >> 6, r = t & 63;
        float* dst = g_kp + ((((size_t)bh * NKT + kt) * 8 + kc) * 64 + r) * 8;
        dst[w0] = k0; dst[w1] = k1;
    }
    // V padded: [bh][kt][r(64)][68]
    {
        int kt = t >> 6, r = t & 63;
        float* dst = g_vp + (((size_t)bh * NKT + kt) * 64 + r) * 68 + d0;
        *(float2*)dst = make_float2(to_tf32(vv.x), to_tf32(vv.y));
    }
}

// =====================================================================
// Flash attention: cp.async double-buffered K/V, pre-packed tf32 inputs.
// grid = (17, B*H). 128 threads (4 warps), m=32/warp, 64-kv tiles.
// Smem: Qp 32768 + 2*Kp 16384 + 2*Vp 17408 = 100352 B -> 2 CTAs/SM.
// =====================================================================
#define QP_F   (8 * 128 * 8)          // 8192 floats
#define KP_F   (8 * 64 * 8)           // 4096 floats
#define VP_F   (64 * 68)              // 4352 floats
#define KBUF_OFF(i) (QP_F + (i) * KP_F)
#define VBUF_OFF(i) (QP_F + 2 * KP_F + (i) * VP_F)
#define ATTN_SMEM ((QP_F + 2 * KP_F + 2 * VP_F) * 4)   // 100352 bytes
__global__ __launch_bounds__(128, 2) void attn_kernel()
{
    extern __shared__ float sm[];

    int qt = blockIdx.x;                // 0..16
    int bh = blockIdx.y;                // 0..31
    int tid = threadIdx.x;
    int warp = tid >> 5, lane = tid & 31;
    int g = lane >> 2, tig = lane & 3;
    int mb = warp * 32;

    uint32_t smb = (uint32_t)__cvta_generic_to_shared(sm);

    const float* Qg = g_qp + ((size_t)bh * NQT + qt) * QP_F;
    const float* Kg = g_kp + (size_t)bh * NKT * KP_F;
    const float* Vg = g_vp + (size_t)bh * NKT * VP_F;

    // ---- issue Q (32KB) + tile0 K/V as group 0
#pragma unroll
    for (int i = 0; i < 16; i++) {
        int c = (tid + i * 128) * 4;                  // float index, 16B chunks
        cp16(smb + c * 4, Qg + c);
    }
    {
#pragma unroll
        for (int i = 0; i < 8; i++) {
            int c = (tid + i * 128) * 4;
            cp16(smb + (KBUF_OFF(0) + c) * 4, Kg + c);
        }
#pragma unroll
        for (int i = 0; i < 9; i++) {
            int idx = tid + i * 128;
            if (idx < VP_F / 4) {
                int c = idx * 4;
                cp16(smb + (VBUF_OFF(0) + c) * 4, Vg + c);
            }
        }
    }
    CP_COMMIT();
    // ---- issue tile1 as group 1
    {
#pragma unroll
        for (int i = 0; i < 8; i++) {
            int c = (tid + i * 128) * 4;
            cp16(smb + (KBUF_OFF(1) + c) * 4, Kg + KP_F + c);
        }
#pragma unroll
        for (int i = 0; i < 9; i++) {
            int idx = tid + i * 128;
            if (idx < VP_F / 4) {
                int c = idx * 4;
                cp16(smb + (VBUF_OFF(1) + c) * 4, Vg + VP_F + c);
            }
        }
    }
    CP_COMMIT();

    float S[2][8][4], O[2][8][4];
    float m_r[2][2], l_r[2][2];
#pragma unroll
    for (int f = 0; f < 2; f++) {
#pragma unroll
        for (int nt = 0; nt < 8; nt++)
#pragma unroll
            for (int r = 0; r < 4; r++) O[f][nt][r] = 0.f;
        m_r[f][0] = m_r[f][1] = -1e30f;
        l_r[f][0] = l_r[f][1] = 0.f;
    }

    for (int kt = 0; kt < NKT; kt++) {
        int cur = kt & 1;
        const float* Kp = sm + KBUF_OFF(cur);
        const float* Vs = sm + VBUF_OFF(cur);

        CP_WAIT1();            // tile kt (and Q on iter 0) resident
        __syncthreads();

        // ---- S = Q . K^T  (warp: m32 x n64, k=64)
#pragma unroll
        for (int f = 0; f < 2; f++)
#pragma unroll
            for (int nt = 0; nt < 8; nt++)
#pragma unroll
                for (int r = 0; r < 4; r++) S[f][nt][r] = 0.f;
#pragma unroll
        for (int ks = 0; ks < 8; ks++) {
            const float* qb = sm + ks * 1024;
            const float* kb = Kp + ks * 512;
            float2 qA0 = *(const float2*)&qb[(mb + g)      * 8 + 2 * tig];
            float2 qA1 = *(const float2*)&qb[(mb + g + 8)  * 8 + 2 * tig];
            float2 qB0 = *(const float2*)&qb[(mb + g + 16) * 8 + 2 * tig];
            float2 qB1 = *(const float2*)&qb[(mb + g + 24) * 8 + 2 * tig];
#pragma unroll
            for (int nt = 0; nt < 8; nt++) {
                float2 b = *(const float2*)&kb[(nt * 8 + g) * 8 + 2 * tig];
                mma_tf32_v(S[0][nt], qA0.x, qA1.x, qA0.y, qA1.y, b.x, b.y);
                mma_tf32_v(S[1][nt], qB0.x, qB1.x, qB0.y, qB1.y, b.x, b.y);
            }
        }

        float biasv = (qt < 16 && kt < 32 && (kt >> 2) > (qt >> 1)) ? 1.0f : 0.0f;

        // ---- online softmax; p kept in S regs
#pragma unroll
        for (int f = 0; f < 2; f++) {
#pragma unroll
            for (int r = 0; r < 2; r++) {
                float mx = -1e30f;
#pragma unroll
                for (int nt = 0; nt < 8; nt++) {
                    S[f][nt][2 * r]     += biasv;
                    S[f][nt][2 * r + 1] += biasv;
                    mx = fmaxf(mx, fmaxf(S[f][nt][2 * r], S[f][nt][2 * r + 1]));
                }
                mx = fmaxf(mx, __shfl_xor_sync(0xffffffffu, mx, 1));
                mx = fmaxf(mx, __shfl_xor_sync(0xffffffffu, mx, 2));
                float mn = fmaxf(m_r[f][r], mx);
                float rs = 0.f;
#pragma unroll
                for (int nt = 0; nt < 8; nt++) {
                    float p0 = __expf(S[f][nt][2 * r]     - mn);
                    float p1 = __expf(S[f][nt][2 * r + 1] - mn);
                    S[f][nt][2 * r]     = p0;
                    S[f][nt][2 * r + 1] = p1;
                    rs += p0 + p1;
                }
                rs += __shfl_xor_sync(0xffffffffu, rs, 1);
                rs += __shfl_xor_sync(0xffffffffu, rs, 2);
                float alpha = __expf(m_r[f][r] - mn);
                l_r[f][r] = l_r[f][r] * alpha + rs;
                m_r[f][r] = mn;
#pragma unroll
                for (int nt = 0; nt < 8; nt++) {
                    O[f][nt][2 * r]     *= alpha;
                    O[f][nt][2 * r + 1] *= alpha;
                }
            }
        }

        // ---- O += P . V  (zero-shuffle slot->kv permutation)
#pragma unroll
        for (int kc = 0; kc < 8; kc++) {
            int r0 = (kc * 8 + 2 * tig) * 68;
            int r1 = r0 + 68;
            float a00 = to_tf32(S[0][kc][0]);
            float a01 = to_tf32(S[0][kc][2]);
            float a02 = to_tf32(S[0][kc][1]);
            float a03 = to_tf32(S[0][kc][3]);
            float a10 = to_tf32(S[1][kc][0]);
            float a11 = to_tf32(S[1][kc][2]);
            float a12 = to_tf32(S[1][kc][1]);
            float a13 = to_tf32(S[1][kc][3]);
#pragma unroll
            for (int nt = 0; nt < 8; nt++) {
                float b0 = Vs[r0 + nt * 8 + g];
                float b1 = Vs[r1 + nt * 8 + g];
                mma_tf32_v(O[0][nt], a00, a01, a02, a03, b0, b1);
                mma_tf32_v(O[1][nt], a10, a11, a12, a13, b0, b1);
            }
        }

        __syncthreads();       // all warps done with buffer cur
        // ---- issue tile kt+2 into cur (empty group if out of range)
        if (kt + 2 < NKT) {
#pragma unroll
            for (int i = 0; i < 8; i++) {
                int c = (tid + i * 128) * 4;
                cp16(smb + (KBUF_OFF(cur) + c) * 4, Kg + (size_t)(kt + 2) * KP_F + c);
            }
#pragma unroll
            for (int i = 0; i < 9; i++) {
                int idx = tid + i * 128;
                if (idx < VP_F / 4) {
                    int c = idx * 4;
                    cp16(smb + (VBUF_OFF(cur) + c) * 4, Vg + (size_t)(kt + 2) * VP_F + c);
                }
            }
        }
        CP_COMMIT();
    }

    // ---- write out: g_x[b][t][h*64 + d]
    int b = bh / HH, h = bh % HH;
#pragma unroll
    for (int f = 0; f < 2; f++) {
        float inv0 = 1.f / l_r[f][0], inv1 = 1.f / l_r[f][1];
        int t0 = qt * QTR + mb + f * 16 + g;
#pragma unroll
        for (int nt = 0; nt < 8; nt++) {
            int col = h * DHH + nt * 8 + 2 * tig;
            *(float2*)(g_x + (size_t)(b * TT + t0) * DD + col) =
                make_float2(O[f][nt][0] * inv0, O[f][nt][1] * inv0);
            *(float2*)(g_x + (size_t)(b * TT + t0 + 8) * DD + col) =
                make_float2(O[f][nt][2] * inv1, O[f][nt][3] * inv1);
        }
    }
}

// =====================================================================
// Launch
// =====================================================================
extern "C" void kernel_launch(void* const* d_in, const int* in_sizes, int n_in,
                              void* d_out, int out_size)
{
    const float* x1    = (const float*)d_in[0];
    const float* x2    = (const float*)d_in[1];
    const float* Wqkv1 = (const float*)d_in[2];
    const float* bqkv1 = (const float*)d_in[3];
    const float* Wqkv2 = (const float*)d_in[4];
    const float* bqkv2 = (const float*)d_in[5];
    const float* Wout1 = (const float*)d_in[6];
    const float* bout1 = (const float*)d_in[7];
    const float* Wout2 = (const float*)d_in[8];
    const float* bout2 = (const float*)d_in[9];
    const float* gq1   = (const float*)d_in[10];
    const float* gk1   = (const float*)d_in[11];
    const float* gq2   = (const float*)d_in[12];
    const float* gk2   = (const float*)d_in[13];
    float* out = (float*)d_out;

    float* p_qkv = nullptr; float* p_x = nullptr;
    cudaGetSymbolAddress((void**)&p_qkv, g_qkv);
    cudaGetSymbolAddress((void**)&p_x, g_x);

    // QKV projections -> [B, T, 3D]  (x1: 32 tiles, x2: 2 tiles, merged)
    sgemm_tf32_dual<<<dim3(ND3 / 128, 34), 256>>>(
        x1, Wqkv1, bqkv1, p_qkv,
        x2, Wqkv2, bqkv2, p_qkv,
        ND3, DD, 32,
        BB * N1L, 0, BB * N1L,  N1L, 0, TT,
        BB * N2L, 0, BB * N2L,  N2L, N1L, TT);

    // RMSNorm + scatter to packed tf32 tile layouts
    rms_scatter_kernel<<<(BB * TT * HH * 32) / 256, 256>>>(gq1, gk1, gq2, gk2);

    // Attention
    cudaFuncSetAttribute(attn_kernel, cudaFuncAttributeMaxDynamicSharedMemorySize, ATTN_SMEM);
    attn_kernel<<<dim3(NQT, BB * HH), 128, ATTN_SMEM>>>();

    // Output projections (out1: 32 tiles, out2: 2 tiles, merged)
    sgemm_tf32_dual<<<dim3(DD / 128, 34), 256>>>(
        p_x, Wout1, bout1, out,
        p_x, Wout2, bout2, out + (size_t)BB * N1L * DD,
        DD, DD, 32,
        N1L, 0, TT,        BB * N1L, 0, BB * N1L,
        N2L, N1L, TT,      BB * N2L, 0, BB * N2L);
}

// round 10
// speedup vs baseline: 2.9618x; 1.0403x over previous
#include <cuda_runtime.h>
#include <math.h>
#include <stdint.h>

// ---------------- problem constants ----------------
#define BB   2
#define N1L  2048
#define N2L  128
#define TT   2176          // N1 + N2
#define DD   1024
#define HH   16
#define DHH  64
#define ND3  3072          // 3*D
#define NKT  34            // T/64 kv tiles
#define QTR  128           // q rows per attn block
#define NQT  17            // T/128 q tiles

// ---------------- scratch (__device__ globals; no allocs allowed) ----------------
__device__ float g_qkv[BB * TT * ND3];            // [B, T, 3*D]
// Packed, tf32-pre-rounded tiles for attention:
// Qp: [bh][qt(17)][kc(8)][r(128)][8]   elem (r,k): off = r*8 + 2*(k&3) + (k>>2)
// Kp: [bh][kt(34)][kc(8)][r(64)][8]    same packing per 64-row tile
// Vp: [bh][kt(34)][r(64)][68]          natural, padded stride 68
__device__ float g_qp[BB * HH * NQT * 8 * 128 * 8];
__device__ float g_kp[BB * HH * NKT * 8 * 64 * 8];
__device__ float g_vp[BB * HH * NKT * 64 * 68];
__device__ float g_x[BB * TT * DD];               // attention output, heads merged

// ---------------- helpers ----------------
__device__ __forceinline__ float to_tf32(float x) {
    uint32_t u;
    asm("cvt.rna.tf32.f32 %0, %1;" : "=r"(u) : "f"(x));
    return __uint_as_float(u);
}

__device__ __forceinline__ void mma_tf32_v(float* c, const float a0, const float a1,
                                           const float a2, const float a3,
                                           const float b0, const float b1) {
    asm volatile(
        "mma.sync.aligned.m16n8k8.row.col.f32.tf32.tf32.f32 "
        "{%0,%1,%2,%3}, {%4,%5,%6,%7}, {%8,%9}, {%0,%1,%2,%3};"
        : "+f"(c[0]), "+f"(c[1]), "+f"(c[2]), "+f"(c[3])
        : "r"(__float_as_uint(a0)), "r"(__float_as_uint(a1)),
          "r"(__float_as_uint(a2)), "r"(__float_as_uint(a3)),
          "r"(__float_as_uint(b0)), "r"(__float_as_uint(b1)));
}

__device__ __forceinline__ void cp16(uint32_t smem_dst, const void* gsrc) {
    asm volatile("cp.async.cg.shared.global [%0], [%1], 16;\n"
                 :: "r"(smem_dst), "l"(gsrc));
}
#define CP_COMMIT() asm volatile("cp.async.commit_group;\n" ::: "memory")
#define CP_WAIT1()  asm volatile("cp.async.wait_group 1;\n" ::: "memory")

// =====================================================================
// Dual-source tf32 SGEMM (unchanged).
// =====================================================================
#define ALD 20
#define BLD 136
__global__ __launch_bounds__(256) void sgemm_tf32_dual(
    const float* __restrict__ A1, const float* __restrict__ W1,
    const float* __restrict__ bias1, float* __restrict__ C1,
    const float* __restrict__ A2, const float* __restrict__ W2,
    const float* __restrict__ bias2, float* __restrict__ C2,
    int N, int K, int split,
    int a_per1, int a_base1, int a_span1, int c_per1, int c_base1, int c_span1,
    int a_per2, int a_base2, int a_span2, int c_per2, int c_base2, int c_span2)
{
    __shared__ float As[2][128 * ALD];
    __shared__ float Bs[2][16 * BLD];

    bool s0 = (blockIdx.y < (unsigned)split);
    const float* A    = s0 ? A1 : A2;
    const float* W    = s0 ? W1 : W2;
    const float* bias = s0 ? bias1 : bias2;
    float* C          = s0 ? C1 : C2;
    int bm     = s0 ? blockIdx.y : blockIdx.y - split;
    int a_per  = s0 ? a_per1  : a_per2;
    int a_base = s0 ? a_base1 : a_base2;
    int a_span = s0 ? a_span1 : a_span2;
    int c_per  = s0 ? c_per1  : c_per2;
    int c_base = s0 ? c_base1 : c_base2;
    int c_span = s0 ? c_span1 : c_span2;

    int tid = threadIdx.x;
    int bn = blockIdx.x;
    int warp = tid >> 5, lane = tid & 31;
    int g = lane >> 2, tig = lane & 3;
    int wm = (warp >> 2) * 64, wn = (warp & 3) * 32;

    int a_row[2], a_kq[2];
    const float* a_ptr[2];
#pragma unroll
    for (int i = 0; i < 2; i++) {
        int idx = tid + i * 256;
        a_row[i] = idx >> 2;
        a_kq[i]  = (idx & 3) * 4;
        int gr = bm * 128 + a_row[i];
        int arow = (gr / a_per) * a_span + a_base + (gr % a_per);
        a_ptr[i] = A + (size_t)arow * K + a_kq[i];
    }
    int b_kr[2], b_nq[2];
    const float* b_ptr[2];
#pragma unroll
    for (int i = 0; i < 2; i++) {
        int idx = tid + i * 256;
        b_kr[i] = idx >> 5;
        b_nq[i] = (idx & 31) * 4;
        b_ptr[i] = W + (size_t)b_kr[i] * N + bn * 128 + b_nq[i];
    }

    float acc[4][4][4];
#pragma unroll
    for (int mt = 0; mt < 4; mt++)
#pragma unroll
        for (int nt = 0; nt < 4; nt++)
#pragma unroll
            for (int r = 0; r < 4; r++) acc[mt][nt][r] = 0.f;

    int ntiles = K >> 4;

    float4 av[2], bv[2];
#pragma unroll
    for (int i = 0; i < 2; i++) {
        av[i] = *(const float4*)(a_ptr[i]);
        bv[i] = *(const float4*)(b_ptr[i]);
    }
#pragma unroll
    for (int i = 0; i < 2; i++) {
        float* as = &As[0][a_row[i] * ALD + a_kq[i]];
        as[0] = to_tf32(av[i].x); as[1] = to_tf32(av[i].y);
        as[2] = to_tf32(av[i].z); as[3] = to_tf32(av[i].w);
        float* bs = &Bs[0][b_kr[i] * BLD + b_nq[i]];
        bs[0] = to_tf32(bv[i].x); bs[1] = to_tf32(bv[i].y);
        bs[2] = to_tf32(bv[i].z); bs[3] = to_tf32(bv[i].w);
    }
    __syncthreads();

    for (int t = 0; t < ntiles; t++) {
        int cur = t & 1;
        if (t + 1 < ntiles) {
            int kk = (t + 1) * 16;
#pragma unroll
            for (int i = 0; i < 2; i++) {
                av[i] = *(const float4*)(a_ptr[i] + kk);
                bv[i] = *(const float4*)(b_ptr[i] + (size_t)kk * N);
            }
        }
#pragma unroll
        for (int ks = 0; ks < 16; ks += 8) {
            float afr[4][4], bfr[4][2];
#pragma unroll
            for (int mt = 0; mt < 4; mt++) {
                int rb = wm + mt * 16;
                afr[mt][0] = As[cur][(rb + g)     * ALD + ks + tig];
                afr[mt][1] = As[cur][(rb + g + 8) * ALD + ks + tig];
                afr[mt][2] = As[cur][(rb + g)     * ALD + ks + tig + 4];
                afr[mt][3] = As[cur][(rb + g + 8) * ALD + ks + tig + 4];
            }
#pragma unroll
            for (int nt = 0; nt < 4; nt++) {
                int nb = wn + nt * 8;
                bfr[nt][0] = Bs[cur][(ks + tig)     * BLD + nb + g];
                bfr[nt][1] = Bs[cur][(ks + tig + 4) * BLD + nb + g];
            }
#pragma unroll
            for (int mt = 0; mt < 4; mt++)
#pragma unroll
                for (int nt = 0; nt < 4; nt++)
                    mma_tf32_v(acc[mt][nt], afr[mt][0], afr[mt][1], afr[mt][2], afr[mt][3],
                               bfr[nt][0], bfr[nt][1]);
        }
        if (t + 1 < ntiles) {
            int nxt = cur ^ 1;
#pragma unroll
            for (int i = 0; i < 2; i++) {
                float* as = &As[nxt][a_row[i] * ALD + a_kq[i]];
                as[0] = to_tf32(av[i].x); as[1] = to_tf32(av[i].y);
                as[2] = to_tf32(av[i].z); as[3] = to_tf32(av[i].w);
                float* bs = &Bs[nxt][b_kr[i] * BLD + b_nq[i]];
                bs[0] = to_tf32(bv[i].x); bs[1] = to_tf32(bv[i].y);
                bs[2] = to_tf32(bv[i].z); bs[3] = to_tf32(bv[i].w);
            }
        }
        __syncthreads();
    }

#pragma unroll
    for (int mt = 0; mt < 4; mt++) {
        int gm0 = bm * 128 + wm + mt * 16 + g;
        int gm1 = gm0 + 8;
        int cr0 = (gm0 / c_per) * c_span + c_base + (gm0 % c_per);
        int cr1 = (gm1 / c_per) * c_span + c_base + (gm1 % c_per);
#pragma unroll
        for (int nt = 0; nt < 4; nt++) {
            int cn = bn * 128 + wn + nt * 8 + 2 * tig;
            float2 bi = *(const float2*)(bias + cn);
            *(float2*)(C + (size_t)cr0 * N + cn) =
                make_float2(acc[mt][nt][0] + bi.x, acc[mt][nt][1] + bi.y);
            *(float2*)(C + (size_t)cr1 * N + cn) =
                make_float2(acc[mt][nt][2] + bi.x, acc[mt][nt][3] + bi.y);
        }
    }
}

// =====================================================================
// RMSNorm(q,k) + scatter into packed tf32 tile layouts. (unchanged)
// =====================================================================
__global__ __launch_bounds__(256) void rms_scatter_kernel(
    const float* __restrict__ gq1, const float* __restrict__ gk1,
    const float* __restrict__ gq2, const float* __restrict__ gk2)
{
    int warp = (blockIdx.x * blockDim.x + threadIdx.x) >> 5;
    int lane = threadIdx.x & 31;
    if (warp >= BB * TT * HH) return;
    int h = warp % HH;
    int bt = warp / HH;
    int t = bt % TT;
    int b = bt / TT;
    int bh = b * HH + h;

    const float* base = g_qkv + (size_t)(b * TT + t) * ND3;
    const float* gq = (t < N1L) ? gq1 : gq2;
    const float* gk = (t < N1L) ? gk1 : gk2;

    int d0 = lane * 2;
    float2 qv = *(const float2*)(base + h * DHH + d0);
    float2 kv = *(const float2*)(base + DD + h * DHH + d0);
    float2 vv = *(const float2*)(base + 2 * DD + h * DHH + d0);

    float ssq = qv.x * qv.x + qv.y * qv.y;
    float ssk = kv.x * kv.x + kv.y * kv.y;
#pragma unroll
    for (int off = 16; off > 0; off >>= 1) {
        ssq += __shfl_xor_sync(0xffffffffu, ssq, off);
        ssk += __shfl_xor_sync(0xffffffffu, ssk, off);
    }
    float rq = rsqrtf(ssq * (1.f / 64.f) + 1e-6f) * 0.125f;
    float rk = rsqrtf(ssk * (1.f / 64.f) + 1e-6f);

    float2 gqv = *(const float2*)(gq + d0);
    float2 gkv = *(const float2*)(gk + d0);

    float q0 = to_tf32(qv.x * rq * gqv.x), q1 = to_tf32(qv.y * rq * gqv.y);
    float k0 = to_tf32(kv.x * rk * gkv.x), k1 = to_tf32(kv.y * rk * gkv.y);

    // packed offsets: elem k within kc chunk -> 2*(k&3) + (k>>2)
    int kc = d0 >> 3;
    int e0 = d0 & 7, e1 = e0 + 1;
    int w0 = 2 * (e0 & 3) + (e0 >> 2);
    int w1 = 2 * (e1 & 3) + (e1 >> 2);

    // Q packed: [bh][qt][kc][r(128)][8]
    {
        int qt = t >> 7, r = t & 127;
        float* dst = g_qp + ((((size_t)bh * NQT + qt) * 8 + kc) * 128 + r) * 8;
        dst[w0] = q0; dst[w1] = q1;
    }
    // K packed: [bh][kt][kc][r(64)][8]
    {
        int kt = t >> 6, r = t & 63;
        float* dst = g_kp + ((((size_t)bh * NKT + kt) * 8 + kc) * 64 + r) * 8;
        dst[w0] = k0; dst[w1] = k1;
    }
    // V padded: [bh][kt][r(64)][68]
    {
        int kt = t >> 6, r = t & 63;
        float* dst = g_vp + (((size_t)bh * NKT + kt) * 64 + r) * 68 + d0;
        *(float2*)dst = make_float2(to_tf32(vv.x), to_tf32(vv.y));
    }
}

// =====================================================================
// Flash attention: cp.async double-buffered K/V, pre-packed tf32 inputs,
// NO online max (scores provably bounded: |s| <= 8 + bias 1 by RMSNorm),
// l reduced across lanes once after the kv loop.
// grid = (17, B*H). 128 threads (4 warps), m=32/warp, 64-kv tiles.
// =====================================================================
#define QP_F   (8 * 128 * 8)          // 8192 floats
#define KP_F   (8 * 64 * 8)           // 4096 floats
#define VP_F   (64 * 68)              // 4352 floats
#define KBUF_OFF(i) (QP_F + (i) * KP_F)
#define VBUF_OFF(i) (QP_F + 2 * KP_F + (i) * VP_F)
#define ATTN_SMEM ((QP_F + 2 * KP_F + 2 * VP_F) * 4)   // 100352 bytes
__global__ __launch_bounds__(128, 2) void attn_kernel()
{
    extern __shared__ float sm[];

    int qt = blockIdx.x;                // 0..16
    int bh = blockIdx.y;                // 0..31
    int tid = threadIdx.x;
    int warp = tid >> 5, lane = tid & 31;
    int g = lane >> 2, tig = lane & 3;
    int mb = warp * 32;

    uint32_t smb = (uint32_t)__cvta_generic_to_shared(sm);

    const float* Qg = g_qp + ((size_t)bh * NQT + qt) * QP_F;
    const float* Kg = g_kp + (size_t)bh * NKT * KP_F;
    const float* Vg = g_vp + (size_t)bh * NKT * VP_F;

    // ---- issue Q (32KB) + tile0 K/V as group 0
#pragma unroll
    for (int i = 0; i < 16; i++) {
        int c = (tid + i * 128) * 4;
        cp16(smb + c * 4, Qg + c);
    }
    {
#pragma unroll
        for (int i = 0; i < 8; i++) {
            int c = (tid + i * 128) * 4;
            cp16(smb + (KBUF_OFF(0) + c) * 4, Kg + c);
        }
#pragma unroll
        for (int i = 0; i < 9; i++) {
            int idx = tid + i * 128;
            if (idx < VP_F / 4) {
                int c = idx * 4;
                cp16(smb + (VBUF_OFF(0) + c) * 4, Vg + c);
            }
        }
    }
    CP_COMMIT();
    // ---- issue tile1 as group 1
    {
#pragma unroll
        for (int i = 0; i < 8; i++) {
            int c = (tid + i * 128) * 4;
            cp16(smb + (KBUF_OFF(1) + c) * 4, Kg + KP_F + c);
        }
#pragma unroll
        for (int i = 0; i < 9; i++) {
            int idx = tid + i * 128;
            if (idx < VP_F / 4) {
                int c = idx * 4;
                cp16(smb + (VBUF_OFF(1) + c) * 4, Vg + VP_F + c);
            }
        }
    }
    CP_COMMIT();

    float S[2][8][4], O[2][8][4];
    float ls[2][2];                    // per-lane partial row sums
#pragma unroll
    for (int f = 0; f < 2; f++) {
#pragma unroll
        for (int nt = 0; nt < 8; nt++)
#pragma unroll
            for (int r = 0; r < 4; r++) O[f][nt][r] = 0.f;
        ls[f][0] = ls[f][1] = 0.f;
    }

    for (int kt = 0; kt < NKT; kt++) {
        int cur = kt & 1;
        const float* Kp = sm + KBUF_OFF(cur);
        const float* Vs = sm + VBUF_OFF(cur);

        CP_WAIT1();            // tile kt (and Q on iter 0) resident
        __syncthreads();

        // ---- S = Q . K^T  (warp: m32 x n64, k=64)
#pragma unroll
        for (int f = 0; f < 2; f++)
#pragma unroll
            for (int nt = 0; nt < 8; nt++)
#pragma unroll
                for (int r = 0; r < 4; r++) S[f][nt][r] = 0.f;
#pragma unroll
        for (int ks = 0; ks < 8; ks++) {
            const float* qb = sm + ks * 1024;
            const float* kb = Kp + ks * 512;
            float2 qA0 = *(const float2*)&qb[(mb + g)      * 8 + 2 * tig];
            float2 qA1 = *(const float2*)&qb[(mb + g + 8)  * 8 + 2 * tig];
            float2 qB0 = *(const float2*)&qb[(mb + g + 16) * 8 + 2 * tig];
            float2 qB1 = *(const float2*)&qb[(mb + g + 24) * 8 + 2 * tig];
#pragma unroll
            for (int nt = 0; nt < 8; nt++) {
                float2 b = *(const float2*)&kb[(nt * 8 + g) * 8 + 2 * tig];
                mma_tf32_v(S[0][nt], qA0.x, qA1.x, qA0.y, qA1.y, b.x, b.y);
                mma_tf32_v(S[1][nt], qB0.x, qB1.x, qB0.y, qB1.y, b.x, b.y);
            }
        }

        float biasv = (qt < 16 && kt < 32 && (kt >> 2) > (qt >> 1)) ? 1.0f : 0.0f;

        // ---- p = exp(s + bias); no max needed (|s| <= 8 guaranteed by RMSNorm)
#pragma unroll
        for (int f = 0; f < 2; f++) {
            float s0 = 0.f, s1 = 0.f;
#pragma unroll
            for (int nt = 0; nt < 8; nt++) {
                float p0 = __expf(S[f][nt][0] + biasv);
                float p1 = __expf(S[f][nt][1] + biasv);
                float p2 = __expf(S[f][nt][2] + biasv);
                float p3 = __expf(S[f][nt][3] + biasv);
                S[f][nt][0] = p0; S[f][nt][1] = p1;
                S[f][nt][2] = p2; S[f][nt][3] = p3;
                s0 += p0 + p1;
                s1 += p2 + p3;
            }
            ls[f][0] += s0;
            ls[f][1] += s1;
        }

        // ---- O += P . V  (zero-shuffle slot->kv permutation)
#pragma unroll
        for (int kc = 0; kc < 8; kc++) {
            int r0 = (kc * 8 + 2 * tig) * 68;
            int r1 = r0 + 68;
            float a00 = to_tf32(S[0][kc][0]);
            float a01 = to_tf32(S[0][kc][2]);
            float a02 = to_tf32(S[0][kc][1]);
            float a03 = to_tf32(S[0][kc][3]);
            float a10 = to_tf32(S[1][kc][0]);
            float a11 = to_tf32(S[1][kc][2]);
            float a12 = to_tf32(S[1][kc][1]);
            float a13 = to_tf32(S[1][kc][3]);
#pragma unroll
            for (int nt = 0; nt < 8; nt++) {
                float b0 = Vs[r0 + nt * 8 + g];
                float b1 = Vs[r1 + nt * 8 + g];
                mma_tf32_v(O[0][nt], a00, a01, a02, a03, b0, b1);
                mma_tf32_v(O[1][nt], a10, a11, a12, a13, b0, b1);
            }
        }

        __syncthreads();       // all warps done with buffer cur
        // ---- issue tile kt+2 into cur (empty group if out of range)
        if (kt + 2 < NKT) {
#pragma unroll
            for (int i = 0; i < 8; i++) {
                int c = (tid + i * 128) * 4;
                cp16(smb + (KBUF_OFF(cur) + c) * 4, Kg + (size_t)(kt + 2) * KP_F + c);
            }
#pragma unroll
            for (int i = 0; i < 9; i++) {
                int idx = tid + i * 128;
                if (idx < VP_F / 4) {
                    int c = idx * 4;
                    cp16(smb + (VBUF_OFF(cur) + c) * 4, Vg + (size_t)(kt + 2) * VP_F + c);
                }
            }
        }
        CP_COMMIT();
    }

    // ---- reduce l across the 4 lanes of each row group (once)
#pragma unroll
    for (int f = 0; f < 2; f++)
#pragma unroll
        for (int r = 0; r < 2; r++) {
            ls[f][r] += __shfl_xor_sync(0xffffffffu, ls[f][r], 1);
            ls[f][r] += __shfl_xor_sync(0xffffffffu, ls[f][r], 2);
        }

    // ---- write out: g_x[b][t][h*64 + d]
    int b = bh / HH, h = bh % HH;
#pragma unroll
    for (int f = 0; f < 2; f++) {
        float inv0 = 1.f / ls[f][0], inv1 = 1.f / ls[f][1];
        int t0 = qt * QTR + mb + f * 16 + g;
#pragma unroll
        for (int nt = 0; nt < 8; nt++) {
            int col = h * DHH + nt * 8 + 2 * tig;
            *(float2*)(g_x + (size_t)(b * TT + t0) * DD + col) =
                make_float2(O[f][nt][0] * inv0, O[f][nt][1] * inv0);
            *(float2*)(g_x + (size_t)(b * TT + t0 + 8) * DD + col) =
                make_float2(O[f][nt][2] * inv1, O[f][nt][3] * inv1);
        }
    }
}

// =====================================================================
// Launch
// =====================================================================
extern "C" void kernel_launch(void* const* d_in, const int* in_sizes, int n_in,
                              void* d_out, int out_size)
{
    const float* x1    = (const float*)d_in[0];
    const float* x2    = (const float*)d_in[1];
    const float* Wqkv1 = (const float*)d_in[2];
    const float* bqkv1 = (const float*)d_in[3];
    const float* Wqkv2 = (const float*)d_in[4];
    const float* bqkv2 = (const float*)d_in[5];
    const float* Wout1 = (const float*)d_in[6];
    const float* bout1 = (const float*)d_in[7];
    const float* Wout2 = (const float*)d_in[8];
    const float* bout2 = (const float*)d_in[9];
    const float* gq1   = (const float*)d_in[10];
    const float* gk1   = (const float*)d_in[11];
    const float* gq2   = (const float*)d_in[12];
    const float* gk2   = (const float*)d_in[13];
    float* out = (float*)d_out;

    float* p_qkv = nullptr; float* p_x = nullptr;
    cudaGetSymbolAddress((void**)&p_qkv, g_qkv);
    cudaGetSymbolAddress((void**)&p_x, g_x);

    // QKV projections -> [B, T, 3D]  (x1: 32 tiles, x2: 2 tiles, merged)
    sgemm_tf32_dual<<<dim3(ND3 / 128, 34), 256>>>(
        x1, Wqkv1, bqkv1, p_qkv,
        x2, Wqkv2, bqkv2, p_qkv,
        ND3, DD, 32,
        BB * N1L, 0, BB * N1L,  N1L, 0, TT,
        BB * N2L, 0, BB * N2L,  N2L, N1L, TT);

    // RMSNorm + scatter to packed tf32 tile layouts
    rms_scatter_kernel<<<(BB * TT * HH * 32) / 256, 256>>>(gq1, gk1, gq2, gk2);

    // Attention
    cudaFuncSetAttribute(attn_kernel, cudaFuncAttributeMaxDynamicSharedMemorySize, ATTN_SMEM);
    attn_kernel<<<dim3(NQT, BB * HH), 128, ATTN_SMEM>>>();

    // Output projections (out1: 32 tiles, out2: 2 tiles, merged)
    sgemm_tf32_dual<<<dim3(DD / 128, 34), 256>>>(
        p_x, Wout1, bout1, out,
        p_x, Wout2, bout2, out + (size_t)BB * N1L * DD,
        DD, DD, 32,
        N1L, 0, TT,        BB * N1L, 0, BB * N1L,
        N2L, N1L, TT,      BB * N2L, 0, BB * N2L);
}

// round 11
// speedup vs baseline: 3.0766x; 1.0388x over previous
#include <cuda_runtime.h>
#include <math.h>
#include <stdint.h>

// ---------------- problem constants ----------------
#define BB   2
#define N1L  2048
#define N2L  128
#define TT   2176          // N1 + N2
#define DD   1024
#define HH   16
#define DHH  64
#define ND3  3072          // 3*D
#define NKT  34            // T/64 kv tiles
#define QTR  128           // q rows per attn block
#define NQT  17            // T/128 q tiles

// ---------------- scratch (__device__ globals; no allocs allowed) ----------------
__device__ float g_qkv[BB * TT * ND3];            // [B, T, 3*D]
// Packed, tf32-pre-rounded tiles for attention:
// Qp: [bh][qt(17)][kc(8)][r(128)][8]   elem (r,k): off = r*8 + 2*(k&3) + (k>>2)
// Kp: [bh][kt(34)][kc(8)][r(64)][8]    same packing per 64-row tile
// Vp: [bh][kt(34)][ (kv>>3)*512 + d*8 + (kv&7) ]   pair-packed for LDS.64 b-frags
__device__ float g_qp[BB * HH * NQT * 8 * 128 * 8];
__device__ float g_kp[BB * HH * NKT * 8 * 64 * 8];
__device__ float g_vp[BB * HH * NKT * 4096];
__device__ float g_x[BB * TT * DD];               // attention output, heads merged

// ---------------- helpers ----------------
__device__ __forceinline__ float to_tf32(float x) {
    uint32_t u;
    asm("cvt.rna.tf32.f32 %0, %1;" : "=r"(u) : "f"(x));
    return __uint_as_float(u);
}

__device__ __forceinline__ void mma_tf32_v(float* c, const float a0, const float a1,
                                           const float a2, const float a3,
                                           const float b0, const float b1) {
    asm volatile(
        "mma.sync.aligned.m16n8k8.row.col.f32.tf32.tf32.f32 "
        "{%0,%1,%2,%3}, {%4,%5,%6,%7}, {%8,%9}, {%0,%1,%2,%3};"
        : "+f"(c[0]), "+f"(c[1]), "+f"(c[2]), "+f"(c[3])
        : "r"(__float_as_uint(a0)), "r"(__float_as_uint(a1)),
          "r"(__float_as_uint(a2)), "r"(__float_as_uint(a3)),
          "r"(__float_as_uint(b0)), "r"(__float_as_uint(b1)));
}

__device__ __forceinline__ void cp16(uint32_t smem_dst, const void* gsrc) {
    asm volatile("cp.async.cg.shared.global [%0], [%1], 16;\n"
                 :: "r"(smem_dst), "l"(gsrc));
}
#define CP_COMMIT() asm volatile("cp.async.commit_group;\n" ::: "memory")
#define CP_WAIT1()  asm volatile("cp.async.wait_group 1;\n" ::: "memory")

// =====================================================================
// Dual-source tf32 SGEMM (unchanged).
// =====================================================================
#define ALD 20
#define BLD 136
__global__ __launch_bounds__(256) void sgemm_tf32_dual(
    const float* __restrict__ A1, const float* __restrict__ W1,
    const float* __restrict__ bias1, float* __restrict__ C1,
    const float* __restrict__ A2, const float* __restrict__ W2,
    const float* __restrict__ bias2, float* __restrict__ C2,
    int N, int K, int split,
    int a_per1, int a_base1, int a_span1, int c_per1, int c_base1, int c_span1,
    int a_per2, int a_base2, int a_span2, int c_per2, int c_base2, int c_span2)
{
    __shared__ float As[2][128 * ALD];
    __shared__ float Bs[2][16 * BLD];

    bool s0 = (blockIdx.y < (unsigned)split);
    const float* A    = s0 ? A1 : A2;
    const float* W    = s0 ? W1 : W2;
    const float* bias = s0 ? bias1 : bias2;
    float* C          = s0 ? C1 : C2;
    int bm     = s0 ? blockIdx.y : blockIdx.y - split;
    int a_per  = s0 ? a_per1  : a_per2;
    int a_base = s0 ? a_base1 : a_base2;
    int a_span = s0 ? a_span1 : a_span2;
    int c_per  = s0 ? c_per1  : c_per2;
    int c_base = s0 ? c_base1 : c_base2;
    int c_span = s0 ? c_span1 : c_span2;

    int tid = threadIdx.x;
    int bn = blockIdx.x;
    int warp = tid >> 5, lane = tid & 31;
    int g = lane >> 2, tig = lane & 3;
    int wm = (warp >> 2) * 64, wn = (warp & 3) * 32;

    int a_row[2], a_kq[2];
    const float* a_ptr[2];
#pragma unroll
    for (int i = 0; i < 2; i++) {
        int idx = tid + i * 256;
        a_row[i] = idx >> 2;
        a_kq[i]  = (idx & 3) * 4;
        int gr = bm * 128 + a_row[i];
        int arow = (gr / a_per) * a_span + a_base + (gr % a_per);
        a_ptr[i] = A + (size_t)arow * K + a_kq[i];
    }
    int b_kr[2], b_nq[2];
    const float* b_ptr[2];
#pragma unroll
    for (int i = 0; i < 2; i++) {
        int idx = tid + i * 256;
        b_kr[i] = idx >> 5;
        b_nq[i] = (idx & 31) * 4;
        b_ptr[i] = W + (size_t)b_kr[i] * N + bn * 128 + b_nq[i];
    }

    float acc[4][4][4];
#pragma unroll
    for (int mt = 0; mt < 4; mt++)
#pragma unroll
        for (int nt = 0; nt < 4; nt++)
#pragma unroll
            for (int r = 0; r < 4; r++) acc[mt][nt][r] = 0.f;

    int ntiles = K >> 4;

    float4 av[2], bv[2];
#pragma unroll
    for (int i = 0; i < 2; i++) {
        av[i] = *(const float4*)(a_ptr[i]);
        bv[i] = *(const float4*)(b_ptr[i]);
    }
#pragma unroll
    for (int i = 0; i < 2; i++) {
        float* as = &As[0][a_row[i] * ALD + a_kq[i]];
        as[0] = to_tf32(av[i].x); as[1] = to_tf32(av[i].y);
        as[2] = to_tf32(av[i].z); as[3] = to_tf32(av[i].w);
        float* bs = &Bs[0][b_kr[i] * BLD + b_nq[i]];
        bs[0] = to_tf32(bv[i].x); bs[1] = to_tf32(bv[i].y);
        bs[2] = to_tf32(bv[i].z); bs[3] = to_tf32(bv[i].w);
    }
    __syncthreads();

    for (int t = 0; t < ntiles; t++) {
        int cur = t & 1;
        if (t + 1 < ntiles) {
            int kk = (t + 1) * 16;
#pragma unroll
            for (int i = 0; i < 2; i++) {
                av[i] = *(const float4*)(a_ptr[i] + kk);
                bv[i] = *(const float4*)(b_ptr[i] + (size_t)kk * N);
            }
        }
#pragma unroll
        for (int ks = 0; ks < 16; ks += 8) {
            float afr[4][4], bfr[4][2];
#pragma unroll
            for (int mt = 0; mt < 4; mt++) {
                int rb = wm + mt * 16;
                afr[mt][0] = As[cur][(rb + g)     * ALD + ks + tig];
                afr[mt][1] = As[cur][(rb + g + 8) * ALD + ks + tig];
                afr[mt][2] = As[cur][(rb + g)     * ALD + ks + tig + 4];
                afr[mt][3] = As[cur][(rb + g + 8) * ALD + ks + tig + 4];
            }
#pragma unroll
            for (int nt = 0; nt < 4; nt++) {
                int nb = wn + nt * 8;
                bfr[nt][0] = Bs[cur][(ks + tig)     * BLD + nb + g];
                bfr[nt][1] = Bs[cur][(ks + tig + 4) * BLD + nb + g];
            }
#pragma unroll
            for (int mt = 0; mt < 4; mt++)
#pragma unroll
                for (int nt = 0; nt < 4; nt++)
                    mma_tf32_v(acc[mt][nt], afr[mt][0], afr[mt][1], afr[mt][2], afr[mt][3],
                               bfr[nt][0], bfr[nt][1]);
        }
        if (t + 1 < ntiles) {
            int nxt = cur ^ 1;
#pragma unroll
            for (int i = 0; i < 2; i++) {
                float* as = &As[nxt][a_row[i] * ALD + a_kq[i]];
                as[0] = to_tf32(av[i].x); as[1] = to_tf32(av[i].y);
                as[2] = to_tf32(av[i].z); as[3] = to_tf32(av[i].w);
                float* bs = &Bs[nxt][b_kr[i] * BLD + b_nq[i]];
                bs[0] = to_tf32(bv[i].x); bs[1] = to_tf32(bv[i].y);
                bs[2] = to_tf32(bv[i].z); bs[3] = to_tf32(bv[i].w);
            }
        }
        __syncthreads();
    }

#pragma unroll
    for (int mt = 0; mt < 4; mt++) {
        int gm0 = bm * 128 + wm + mt * 16 + g;
        int gm1 = gm0 + 8;
        int cr0 = (gm0 / c_per) * c_span + c_base + (gm0 % c_per);
        int cr1 = (gm1 / c_per) * c_span + c_base + (gm1 % c_per);
#pragma unroll
        for (int nt = 0; nt < 4; nt++) {
            int cn = bn * 128 + wn + nt * 8 + 2 * tig;
            float2 bi = *(const float2*)(bias + cn);
            *(float2*)(C + (size_t)cr0 * N + cn) =
                make_float2(acc[mt][nt][0] + bi.x, acc[mt][nt][1] + bi.y);
            *(float2*)(C + (size_t)cr1 * N + cn) =
                make_float2(acc[mt][nt][2] + bi.x, acc[mt][nt][3] + bi.y);
        }
    }
}

// =====================================================================
// RMSNorm(q,k) + scatter into packed tf32 tile layouts.
// =====================================================================
__global__ __launch_bounds__(256) void rms_scatter_kernel(
    const float* __restrict__ gq1, const float* __restrict__ gk1,
    const float* __restrict__ gq2, const float* __restrict__ gk2)
{
    int warp = (blockIdx.x * blockDim.x + threadIdx.x) >> 5;
    int lane = threadIdx.x & 31;
    if (warp >= BB * TT * HH) return;
    int h = warp % HH;
    int bt = warp / HH;
    int t = bt % TT;
    int b = bt / TT;
    int bh = b * HH + h;

    const float* base = g_qkv + (size_t)(b * TT + t) * ND3;
    const float* gq = (t < N1L) ? gq1 : gq2;
    const float* gk = (t < N1L) ? gk1 : gk2;

    int d0 = lane * 2;
    float2 qv = *(const float2*)(base + h * DHH + d0);
    float2 kv = *(const float2*)(base + DD + h * DHH + d0);
    float2 vv = *(const float2*)(base + 2 * DD + h * DHH + d0);

    float ssq = qv.x * qv.x + qv.y * qv.y;
    float ssk = kv.x * kv.x + kv.y * kv.y;
#pragma unroll
    for (int off = 16; off > 0; off >>= 1) {
        ssq += __shfl_xor_sync(0xffffffffu, ssq, off);
        ssk += __shfl_xor_sync(0xffffffffu, ssk, off);
    }
    float rq = rsqrtf(ssq * (1.f / 64.f) + 1e-6f) * 0.125f;
    float rk = rsqrtf(ssk * (1.f / 64.f) + 1e-6f);

    float2 gqv = *(const float2*)(gq + d0);
    float2 gkv = *(const float2*)(gk + d0);

    float q0 = to_tf32(qv.x * rq * gqv.x), q1 = to_tf32(qv.y * rq * gqv.y);
    float k0 = to_tf32(kv.x * rk * gkv.x), k1 = to_tf32(kv.y * rk * gkv.y);

    // packed offsets: elem k within kc chunk -> 2*(k&3) + (k>>2)
    int kc = d0 >> 3;
    int e0 = d0 & 7, e1 = e0 + 1;
    int w0 = 2 * (e0 & 3) + (e0 >> 2);
    int w1 = 2 * (e1 & 3) + (e1 >> 2);

    // Q packed: [bh][qt][kc][r(128)][8]
    {
        int qt = t >> 7, r = t & 127;
        float* dst = g_qp + ((((size_t)bh * NQT + qt) * 8 + kc) * 128 + r) * 8;
        dst[w0] = q0; dst[w1] = q1;
    }
    // K packed: [bh][kt][kc][r(64)][8]
    {
        int kt = t >> 6, r = t & 63;
        float* dst = g_kp + ((((size_t)bh * NKT + kt) * 8 + kc) * 64 + r) * 8;
        dst[w0] = k0; dst[w1] = k1;
    }
    // V pair-packed: off = (kv>>3)*512 + d*8 + (kv&7)
    {
        int kt = t >> 6, r = t & 63;
        float* dst = g_vp + ((size_t)bh * NKT + kt) * 4096 + (r >> 3) * 512 + (r & 7);
        dst[d0 * 8]       = to_tf32(vv.x);
        dst[d0 * 8 + 8]   = to_tf32(vv.y);
    }
}

// =====================================================================
// Flash attention: Q fragments in registers (loaded once via LDG),
// cp.async double-buffered K/V, pair-packed V (LDS.64 b-frags), no max.
// grid = (17, B*H). 128 threads (4 warps), m=32/warp, 64-kv tiles.
// Smem: 2*K 16KB + 2*V 16KB = 65536 B -> 2 CTAs/SM.
// =====================================================================
#define QP_F   (8 * 128 * 8)          // 8192 floats per q-tile in gmem
#define KP_F   4096
#define VP_F   4096
#define KBUF_OFF(i) ((i) * 4096)
#define VBUF_OFF(i) (8192 + (i) * 4096)
#define ATTN_SMEM (16384 * 4)         // 65536 bytes
__global__ __launch_bounds__(128, 2) void attn_kernel()
{
    extern __shared__ float sm[];

    int qt = blockIdx.x;                // 0..16
    int bh = blockIdx.y;                // 0..31
    int tid = threadIdx.x;
    int warp = tid >> 5, lane = tid & 31;
    int g = lane >> 2, tig = lane & 3;
    int mb = warp * 32;

    uint32_t smb = (uint32_t)__cvta_generic_to_shared(sm);

    const float* Qg = g_qp + ((size_t)bh * NQT + qt) * QP_F;
    const float* Kg = g_kp + (size_t)bh * NKT * KP_F;
    const float* Vg = g_vp + (size_t)bh * NKT * VP_F;

    // ---- issue tile0 K/V as group 0, tile1 as group 1
#pragma unroll
    for (int i = 0; i < 8; i++) {
        int c = (tid + i * 128) * 4;
        cp16(smb + (KBUF_OFF(0) + c) * 4, Kg + c);
        cp16(smb + (VBUF_OFF(0) + c) * 4, Vg + c);
    }
    CP_COMMIT();
#pragma unroll
    for (int i = 0; i < 8; i++) {
        int c = (tid + i * 128) * 4;
        cp16(smb + (KBUF_OFF(1) + c) * 4, Kg + KP_F + c);
        cp16(smb + (VBUF_OFF(1) + c) * 4, Vg + VP_F + c);
    }
    CP_COMMIT();

    // ---- load Q fragments into registers (once; overlaps cp.async)
    float2 qf[8][4];
#pragma unroll
    for (int ks = 0; ks < 8; ks++) {
        const float* qb = Qg + ks * 1024;
        qf[ks][0] = *(const float2*)&qb[(mb + g)      * 8 + 2 * tig];
        qf[ks][1] = *(const float2*)&qb[(mb + g + 8)  * 8 + 2 * tig];
        qf[ks][2] = *(const float2*)&qb[(mb + g + 16) * 8 + 2 * tig];
        qf[ks][3] = *(const float2*)&qb[(mb + g + 24) * 8 + 2 * tig];
    }

    float S[2][8][4], O[2][8][4];
    float ls[2][2];
#pragma unroll
    for (int f = 0; f < 2; f++) {
#pragma unroll
        for (int nt = 0; nt < 8; nt++)
#pragma unroll
            for (int r = 0; r < 4; r++) O[f][nt][r] = 0.f;
        ls[f][0] = ls[f][1] = 0.f;
    }

    for (int kt = 0; kt < NKT; kt++) {
        int cur = kt & 1;
        const float* Kp = sm + KBUF_OFF(cur);
        const float* Vs = sm + VBUF_OFF(cur);

        CP_WAIT1();
        __syncthreads();

        // ---- S = Q . K^T  (warp: m32 x n64, k=64); Q from registers
#pragma unroll
        for (int f = 0; f < 2; f++)
#pragma unroll
            for (int nt = 0; nt < 8; nt++)
#pragma unroll
                for (int r = 0; r < 4; r++) S[f][nt][r] = 0.f;
#pragma unroll
        for (int ks = 0; ks < 8; ks++) {
            const float* kb = Kp + ks * 512;
            float2 a0 = qf[ks][0], a1 = qf[ks][1];
            float2 a2 = qf[ks][2], a3 = qf[ks][3];
#pragma unroll
            for (int nt = 0; nt < 8; nt++) {
                float2 b = *(const float2*)&kb[(nt * 8 + g) * 8 + 2 * tig];
                mma_tf32_v(S[0][nt], a0.x, a1.x, a0.y, a1.y, b.x, b.y);
                mma_tf32_v(S[1][nt], a2.x, a3.x, a2.y, a3.y, b.x, b.y);
            }
        }

        float biasv = (qt < 16 && kt < 32 && (kt >> 2) > (qt >> 1)) ? 1.0f : 0.0f;

        // ---- p = exp(s + bias); no max needed (|s| <= 8 by RMSNorm bound)
#pragma unroll
        for (int f = 0; f < 2; f++) {
            float s0 = 0.f, s1 = 0.f;
#pragma unroll
            for (int nt = 0; nt < 8; nt++) {
                float p0 = __expf(S[f][nt][0] + biasv);
                float p1 = __expf(S[f][nt][1] + biasv);
                float p2 = __expf(S[f][nt][2] + biasv);
                float p3 = __expf(S[f][nt][3] + biasv);
                S[f][nt][0] = p0; S[f][nt][1] = p1;
                S[f][nt][2] = p2; S[f][nt][3] = p3;
                s0 += p0 + p1;
                s1 += p2 + p3;
            }
            ls[f][0] += s0;
            ls[f][1] += s1;
        }

        // ---- O += P . V  (zero-shuffle; V pair-packed -> LDS.64 b-frags)
#pragma unroll
        for (int kc = 0; kc < 8; kc++) {
            const float* vb = Vs + kc * 512 + 2 * tig;
            float a00 = to_tf32(S[0][kc][0]);
            float a01 = to_tf32(S[0][kc][2]);
            float a02 = to_tf32(S[0][kc][1]);
            float a03 = to_tf32(S[0][kc][3]);
            float a10 = to_tf32(S[1][kc][0]);
            float a11 = to_tf32(S[1][kc][2]);
            float a12 = to_tf32(S[1][kc][1]);
            float a13 = to_tf32(S[1][kc][3]);
#pragma unroll
            for (int nt = 0; nt < 8; nt++) {
                float2 b = *(const float2*)&vb[(nt * 8 + g) * 8];
                mma_tf32_v(O[0][nt], a00, a01, a02, a03, b.x, b.y);
                mma_tf32_v(O[1][nt], a10, a11, a12, a13, b.x, b.y);
            }
        }

        __syncthreads();
        // ---- issue tile kt+2 into cur (empty group if out of range)
        if (kt + 2 < NKT) {
#pragma unroll
            for (int i = 0; i < 8; i++) {
                int c = (tid + i * 128) * 4;
                cp16(smb + (KBUF_OFF(cur) + c) * 4, Kg + (size_t)(kt + 2) * KP_F + c);
                cp16(smb + (VBUF_OFF(cur) + c) * 4, Vg + (size_t)(kt + 2) * VP_F + c);
            }
        }
        CP_COMMIT();
    }

    // ---- reduce l across the 4 lanes of each row group (once)
#pragma unroll
    for (int f = 0; f < 2; f++)
#pragma unroll
        for (int r = 0; r < 2; r++) {
            ls[f][r] += __shfl_xor_sync(0xffffffffu, ls[f][r], 1);
            ls[f][r] += __shfl_xor_sync(0xffffffffu, ls[f][r], 2);
        }

    // ---- write out: g_x[b][t][h*64 + d]
    int b = bh / HH, h = bh % HH;
#pragma unroll
    for (int f = 0; f < 2; f++) {
        float inv0 = 1.f / ls[f][0], inv1 = 1.f / ls[f][1];
        int t0 = qt * QTR + mb + f * 16 + g;
#pragma unroll
        for (int nt = 0; nt < 8; nt++) {
            int col = h * DHH + nt * 8 + 2 * tig;
            *(float2*)(g_x + (size_t)(b * TT + t0) * DD + col) =
                make_float2(O[f][nt][0] * inv0, O[f][nt][1] * inv0);
            *(float2*)(g_x + (size_t)(b * TT + t0 + 8) * DD + col) =
                make_float2(O[f][nt][2] * inv1, O[f][nt][3] * inv1);
        }
    }
}

// =====================================================================
// Launch
// =====================================================================
extern "C" void kernel_launch(void* const* d_in, const int* in_sizes, int n_in,
                              void* d_out, int out_size)
{
    const float* x1    = (const float*)d_in[0];
    const float* x2    = (const float*)d_in[1];
    const float* Wqkv1 = (const float*)d_in[2];
    const float* bqkv1 = (const float*)d_in[3];
    const float* Wqkv2 = (const float*)d_in[4];
    const float* bqkv2 = (const float*)d_in[5];
    const float* Wout1 = (const float*)d_in[6];
    const float* bout1 = (const float*)d_in[7];
    const float* Wout2 = (const float*)d_in[8];
    const float* bout2 = (const float*)d_in[9];
    const float* gq1   = (const float*)d_in[10];
    const float* gk1   = (const float*)d_in[11];
    const float* gq2   = (const float*)d_in[12];
    const float* gk2   = (const float*)d_in[13];
    float* out = (float*)d_out;

    float* p_qkv = nullptr; float* p_x = nullptr;
    cudaGetSymbolAddress((void**)&p_qkv, g_qkv);
    cudaGetSymbolAddress((void**)&p_x, g_x);

    // QKV projections -> [B, T, 3D]  (x1: 32 tiles, x2: 2 tiles, merged)
    sgemm_tf32_dual<<<dim3(ND3 / 128, 34), 256>>>(
        x1, Wqkv1, bqkv1, p_qkv,
        x2, Wqkv2, bqkv2, p_qkv,
        ND3, DD, 32,
        BB * N1L, 0, BB * N1L,  N1L, 0, TT,
        BB * N2L, 0, BB * N2L,  N2L, N1L, TT);

    // RMSNorm + scatter to packed tf32 tile layouts
    rms_scatter_kernel<<<(BB * TT * HH * 32) / 256, 256>>>(gq1, gk1, gq2, gk2);

    // Attention
    cudaFuncSetAttribute(attn_kernel, cudaFuncAttributeMaxDynamicSharedMemorySize, ATTN_SMEM);
    attn_kernel<<<dim3(NQT, BB * HH), 128, ATTN_SMEM>>>();

    // Output projections (out1: 32 tiles, out2: 2 tiles, merged)
    sgemm_tf32_dual<<<dim3(DD / 128, 34), 256>>>(
        p_x, Wout1, bout1, out,
        p_x, Wout2, bout2, out + (size_t)BB * N1L * DD,
        DD, DD, 32,
        N1L, 0, TT,        BB * N1L, 0, BB * N1L,
        N2L, N1L, TT,      BB * N2L, 0, BB * N2L);
}

// round 13
// speedup vs baseline: 3.3300x; 1.0823x over previous
#include <cuda_runtime.h>
#include <math.h>
#include <stdint.h>

// ---------------- problem constants ----------------
#define BB   2
#define N1L  2048
#define N2L  128
#define TT   2176          // N1 + N2
#define DD   1024
#define HH   16
#define DHH  64
#define ND3  3072          // 3*D
#define NKT  34            // T/64 kv tiles
#define QTR  128           // q rows per attn block
#define NQT  17            // T/128 q tiles

// ---------------- scratch (__device__ globals; no allocs allowed) ----------------
// Packed, tf32-pre-rounded tiles for attention:
// Qp: [bh][qt(17)][kc(8)][r(128)][8]   elem (r,k): slot = 2*((k&7)&3) + ((k&7)>>2)
// Kp: [bh][kt(34)][kc(8)][r(64)][8]    same packing per 64-row tile
// Vp: [bh][kt(34)][ (kv>>3)*512 + d*8 + (kv&7) ]   pair-packed for LDS.64 b-frags
__device__ float g_qp[BB * HH * NQT * 8 * 128 * 8];
__device__ float g_kp[BB * HH * NKT * 8 * 64 * 8];
__device__ float g_vp[BB * HH * NKT * 4096];
__device__ float g_x[BB * TT * DD];               // attention output, heads merged

// ---------------- helpers ----------------
__device__ __forceinline__ float to_tf32(float x) {
    uint32_t u;
    asm("cvt.rna.tf32.f32 %0, %1;" : "=r"(u) : "f"(x));
    return __uint_as_float(u);
}

__device__ __forceinline__ void mma_tf32_v(float* c, const float a0, const float a1,
                                           const float a2, const float a3,
                                           const float b0, const float b1) {
    asm volatile(
        "mma.sync.aligned.m16n8k8.row.col.f32.tf32.tf32.f32 "
        "{%0,%1,%2,%3}, {%4,%5,%6,%7}, {%8,%9}, {%0,%1,%2,%3};"
        : "+f"(c[0]), "+f"(c[1]), "+f"(c[2]), "+f"(c[3])
        : "r"(__float_as_uint(a0)), "r"(__float_as_uint(a1)),
          "r"(__float_as_uint(a2)), "r"(__float_as_uint(a3)),
          "r"(__float_as_uint(b0)), "r"(__float_as_uint(b1)));
}

__device__ __forceinline__ void cp16(uint32_t smem_dst, const void* gsrc) {
    asm volatile("cp.async.cg.shared.global [%0], [%1], 16;\n"
                 :: "r"(smem_dst), "l"(gsrc));
}
#define CP_COMMIT() asm volatile("cp.async.commit_group;\n" ::: "memory")
#define CP_WAIT1()  asm volatile("cp.async.wait_group 1;\n" ::: "memory")

#define ALD 20
#define BLD 136

// =====================================================================
// QKV GEMM with FUSED RMSNorm + packed scatter epilogue.
// BM=128, BN=128, BK=16; grid (24, 34): y<32 -> x1 set, else x2 set.
// bn region: 0..7 = q, 8..15 = k, 16..23 = v. Each q/k block = 2 heads.
// =====================================================================
__global__ __launch_bounds__(256) void qkv_gemm_fused(
    const float* __restrict__ A1, const float* __restrict__ W1,
    const float* __restrict__ bias1,
    const float* __restrict__ A2, const float* __restrict__ W2,
    const float* __restrict__ bias2,
    const float* __restrict__ gq1, const float* __restrict__ gk1,
    const float* __restrict__ gq2, const float* __restrict__ gk2)
{
    __shared__ float As[2][128 * ALD];
    __shared__ float Bs[2][16 * BLD];
    __shared__ float red[128][2][2];   // [row][head-in-block][col-half]

    const int N = ND3, K = DD;
    bool s0 = (blockIdx.y < 32);
    const float* A    = s0 ? A1 : A2;
    const float* W    = s0 ? W1 : W2;
    const float* bias = s0 ? bias1 : bias2;
    int bm = s0 ? blockIdx.y : blockIdx.y - 32;

    int tid = threadIdx.x;
    int bn = blockIdx.x;
    int warp = tid >> 5, lane = tid & 31;
    int g = lane >> 2, tig = lane & 3;
    int wm = (warp >> 2) * 64, wn = (warp & 3) * 32;

    // A rows are identity for both sets
    int a_row[2], a_kq[2];
    const float* a_ptr[2];
#pragma unroll
    for (int i = 0; i < 2; i++) {
        int idx = tid + i * 256;
        a_row[i] = idx >> 2;
        a_kq[i]  = (idx & 3) * 4;
        a_ptr[i] = A + (size_t)(bm * 128 + a_row[i]) * K + a_kq[i];
    }
    int b_kr[2], b_nq[2];
    const float* b_ptr[2];
#pragma unroll
    for (int i = 0; i < 2; i++) {
        int idx = tid + i * 256;
        b_kr[i] = idx >> 5;
        b_nq[i] = (idx & 31) * 4;
        b_ptr[i] = W + (size_t)b_kr[i] * N + bn * 128 + b_nq[i];
    }

    float acc[4][4][4];
#pragma unroll
    for (int mt = 0; mt < 4; mt++)
#pragma unroll
        for (int nt = 0; nt < 4; nt++)
#pragma unroll
            for (int r = 0; r < 4; r++) acc[mt][nt][r] = 0.f;

    int ntiles = K >> 4;
    float4 av[2], bv[2];
#pragma unroll
    for (int i = 0; i < 2; i++) {
        av[i] = *(const float4*)(a_ptr[i]);
        bv[i] = *(const float4*)(b_ptr[i]);
    }
#pragma unroll
    for (int i = 0; i < 2; i++) {
        float* as = &As[0][a_row[i] * ALD + a_kq[i]];
        as[0] = to_tf32(av[i].x); as[1] = to_tf32(av[i].y);
        as[2] = to_tf32(av[i].z); as[3] = to_tf32(av[i].w);
        float* bs = &Bs[0][b_kr[i] * BLD + b_nq[i]];
        bs[0] = to_tf32(bv[i].x); bs[1] = to_tf32(bv[i].y);
        bs[2] = to_tf32(bv[i].z); bs[3] = to_tf32(bv[i].w);
    }
    __syncthreads();

    for (int t = 0; t < ntiles; t++) {
        int cur = t & 1;
        if (t + 1 < ntiles) {
            int kk = (t + 1) * 16;
#pragma unroll
            for (int i = 0; i < 2; i++) {
                av[i] = *(const float4*)(a_ptr[i] + kk);
                bv[i] = *(const float4*)(b_ptr[i] + (size_t)kk * N);
            }
        }
#pragma unroll
        for (int ks = 0; ks < 16; ks += 8) {
            float afr[4][4], bfr[4][2];
#pragma unroll
            for (int mt = 0; mt < 4; mt++) {
                int rb = wm + mt * 16;
                afr[mt][0] = As[cur][(rb + g)     * ALD + ks + tig];
                afr[mt][1] = As[cur][(rb + g + 8) * ALD + ks + tig];
                afr[mt][2] = As[cur][(rb + g)     * ALD + ks + tig + 4];
                afr[mt][3] = As[cur][(rb + g + 8) * ALD + ks + tig + 4];
            }
#pragma unroll
            for (int nt = 0; nt < 4; nt++) {
                int nb = wn + nt * 8;
                bfr[nt][0] = Bs[cur][(ks + tig)     * BLD + nb + g];
                bfr[nt][1] = Bs[cur][(ks + tig + 4) * BLD + nb + g];
            }
#pragma unroll
            for (int mt = 0; mt < 4; mt++)
#pragma unroll
                for (int nt = 0; nt < 4; nt++)
                    mma_tf32_v(acc[mt][nt], afr[mt][0], afr[mt][1], afr[mt][2], afr[mt][3],
                               bfr[nt][0], bfr[nt][1]);
        }
        if (t + 1 < ntiles) {
            int nxt = cur ^ 1;
#pragma unroll
            for (int i = 0; i < 2; i++) {
                float* as = &As[nxt][a_row[i] * ALD + a_kq[i]];
                as[0] = to_tf32(av[i].x); as[1] = to_tf32(av[i].y);
                as[2] = to_tf32(av[i].z); as[3] = to_tf32(av[i].w);
                float* bs = &Bs[nxt][b_kr[i] * BLD + b_nq[i]];
                bs[0] = to_tf32(bv[i].x); bs[1] = to_tf32(bv[i].y);
                bs[2] = to_tf32(bv[i].z); bs[3] = to_tf32(bv[i].w);
            }
        }
        __syncthreads();
    }

    // ================= fused epilogue =================
    // add bias
#pragma unroll
    for (int nt = 0; nt < 4; nt++) {
        int cn = bn * 128 + wn + nt * 8 + 2 * tig;
        float2 bi = *(const float2*)(bias + cn);
#pragma unroll
        for (int mt = 0; mt < 4; mt++) {
            acc[mt][nt][0] += bi.x; acc[mt][nt][1] += bi.y;
            acc[mt][nt][2] += bi.x; acc[mt][nt][3] += bi.y;
        }
    }

    int region = bn >> 3;                 // 0=q, 1=k, 2=v (uniform per block)
    int hsel  = (warp & 3) >> 1;          // head within block
    int part  = warp & 1;                 // 32-col half within head
    int head  = ((bn & 7) << 1) + hsel;
    int dbase = (warp & 1) * 32;          // d offset within head

    if (region < 2) {
        // partial sums of squares -> quad reduce -> smem
#pragma unroll
        for (int mt = 0; mt < 4; mt++) {
#pragma unroll
            for (int half = 0; half < 2; half++) {
                float ps = 0.f;
#pragma unroll
                for (int nt = 0; nt < 4; nt++) {
                    float v0 = acc[mt][nt][2 * half];
                    float v1 = acc[mt][nt][2 * half + 1];
                    ps += v0 * v0 + v1 * v1;
                }
                ps += __shfl_xor_sync(0xffffffffu, ps, 1);
                ps += __shfl_xor_sync(0xffffffffu, ps, 2);
                if (tig == 0)
                    red[wm + mt * 16 + g + 8 * half][hsel][part] = ps;
            }
        }
        __syncthreads();

        const float* gvec = (region == 0) ? (s0 ? gq1 : gq2) : (s0 ? gk1 : gk2);
        float scl = (region == 0) ? 0.125f : 1.0f;

        // slot indices within the packed 8-group for e=2tig, 2tig+1
        int e0 = 2 * tig;
        int sl0 = 2 * (e0 & 3) + (e0 >> 2);
        int sl1 = 2 * ((e0 + 1) & 3) + ((e0 + 1) >> 2);

#pragma unroll
        for (int mt = 0; mt < 4; mt++) {
#pragma unroll
            for (int half = 0; half < 2; half++) {
                int rloc = wm + mt * 16 + g + 8 * half;
                int gm = bm * 128 + rloc;
                int b, tt;
                if (s0) { b = gm >> 11; tt = gm & 2047; }
                else    { b = gm >> 7;  tt = 2048 + (gm & 127); }
                float ssum = red[rloc][hsel][0] + red[rloc][hsel][1];
                float rn = rsqrtf(ssum * (1.f / 64.f) + 1e-6f) * scl;
                int bh = b * HH + head;
#pragma unroll
                for (int nt = 0; nt < 4; nt++) {
                    int d = dbase + nt * 8 + 2 * tig;
                    float2 gv = *(const float2*)(gvec + d);
                    float v0 = to_tf32(acc[mt][nt][2 * half]     * rn * gv.x);
                    float v1 = to_tf32(acc[mt][nt][2 * half + 1] * rn * gv.y);
                    int kc = d >> 3;
                    if (region == 0) {
                        int qt = tt >> 7, r = tt & 127;
                        float* dst = g_qp + ((((size_t)bh * NQT + qt) * 8 + kc) * 128 + r) * 8;
                        dst[sl0] = v0; dst[sl1] = v1;
                    } else {
                        int kt = tt >> 6, r = tt & 63;
                        float* dst = g_kp + ((((size_t)bh * NKT + kt) * 8 + kc) * 64 + r) * 8;
                        dst[sl0] = v0; dst[sl1] = v1;
                    }
                }
            }
        }
    } else {
        // V: straight pack, no norm
#pragma unroll
        for (int mt = 0; mt < 4; mt++) {
#pragma unroll
            for (int half = 0; half < 2; half++) {
                int rloc = wm + mt * 16 + g + 8 * half;
                int gm = bm * 128 + rloc;
                int b, tt;
                if (s0) { b = gm >> 11; tt = gm & 2047; }
                else    { b = gm >> 7;  tt = 2048 + (gm & 127); }
                int bh = b * HH + head;
                int kt = tt >> 6, r = tt & 63;
                float* base_v = g_vp + ((size_t)bh * NKT + kt) * 4096 + (r >> 3) * 512 + (r & 7);
#pragma unroll
                for (int nt = 0; nt < 4; nt++) {
                    int d = dbase + nt * 8 + 2 * tig;
                    base_v[d * 8]     = to_tf32(acc[mt][nt][2 * half]);
                    base_v[d * 8 + 8] = to_tf32(acc[mt][nt][2 * half + 1]);
                }
            }
        }
    }
}

// =====================================================================
// Dual-source tf32 SGEMM (unchanged) — used for the output projections.
// =====================================================================
__global__ __launch_bounds__(256) void sgemm_tf32_dual(
    const float* __restrict__ A1, const float* __restrict__ W1,
    const float* __restrict__ bias1, float* __restrict__ C1,
    const float* __restrict__ A2, const float* __restrict__ W2,
    const float* __restrict__ bias2, float* __restrict__ C2,
    int N, int K, int split,
    int a_per1, int a_base1, int a_span1, int c_per1, int c_base1, int c_span1,
    int a_per2, int a_base2, int a_span2, int c_per2, int c_base2, int c_span2)
{
    __shared__ float As[2][128 * ALD];
    __shared__ float Bs[2][16 * BLD];

    bool s0 = (blockIdx.y < (unsigned)split);
    const float* A    = s0 ? A1 : A2;
    const float* W    = s0 ? W1 : W2;
    const float* bias = s0 ? bias1 : bias2;
    float* C          = s0 ? C1 : C2;
    int bm     = s0 ? blockIdx.y : blockIdx.y - split;
    int a_per  = s0 ? a_per1  : a_per2;
    int a_base = s0 ? a_base1 : a_base2;
    int a_span = s0 ? a_span1 : a_span2;
    int c_per  = s0 ? c_per1  : c_per2;
    int c_base = s0 ? c_base1 : c_base2;
    int c_span = s0 ? c_span1 : c_span2;

    int tid = threadIdx.x;
    int bn = blockIdx.x;
    int warp = tid >> 5, lane = tid & 31;
    int g = lane >> 2, tig = lane & 3;
    int wm = (warp >> 2) * 64, wn = (warp & 3) * 32;

    int a_row[2], a_kq[2];
    const float* a_ptr[2];
#pragma unroll
    for (int i = 0; i < 2; i++) {
        int idx = tid + i * 256;
        a_row[i] = idx >> 2;
        a_kq[i]  = (idx & 3) * 4;
        int gr = bm * 128 + a_row[i];
        int arow = (gr / a_per) * a_span + a_base + (gr % a_per);
        a_ptr[i] = A + (size_t)arow * K + a_kq[i];
    }
    int b_kr[2], b_nq[2];
    const float* b_ptr[2];
#pragma unroll
    for (int i = 0; i < 2; i++) {
        int idx = tid + i * 256;
        b_kr[i] = idx >> 5;
        b_nq[i] = (idx & 31) * 4;
        b_ptr[i] = W + (size_t)b_kr[i] * N + bn * 128 + b_nq[i];
    }

    float acc[4][4][4];
#pragma unroll
    for (int mt = 0; mt < 4; mt++)
#pragma unroll
        for (int nt = 0; nt < 4; nt++)
#pragma unroll
            for (int r = 0; r < 4; r++) acc[mt][nt][r] = 0.f;

    int ntiles = K >> 4;
    float4 av[2], bv[2];
#pragma unroll
    for (int i = 0; i < 2; i++) {
        av[i] = *(const float4*)(a_ptr[i]);
        bv[i] = *(const float4*)(b_ptr[i]);
    }
#pragma unroll
    for (int i = 0; i < 2; i++) {
        float* as = &As[0][a_row[i] * ALD + a_kq[i]];
        as[0] = to_tf32(av[i].x); as[1] = to_tf32(av[i].y);
        as[2] = to_tf32(av[i].z); as[3] = to_tf32(av[i].w);
        float* bs = &Bs[0][b_kr[i] * BLD + b_nq[i]];
        bs[0] = to_tf32(bv[i].x); bs[1] = to_tf32(bv[i].y);
        bs[2] = to_tf32(bv[i].z); bs[3] = to_tf32(bv[i].w);
    }
    __syncthreads();

    for (int t = 0; t < ntiles; t++) {
        int cur = t & 1;
        if (t + 1 < ntiles) {
            int kk = (t + 1) * 16;
#pragma unroll
            for (int i = 0; i < 2; i++) {
                av[i] = *(const float4*)(a_ptr[i] + kk);
                bv[i] = *(const float4*)(b_ptr[i] + (size_t)kk * N);
            }
        }
#pragma unroll
        for (int ks = 0; ks < 16; ks += 8) {
            float afr[4][4], bfr[4][2];
#pragma unroll
            for (int mt = 0; mt < 4; mt++) {
                int rb = wm + mt * 16;
                afr[mt][0] = As[cur][(rb + g)     * ALD + ks + tig];
                afr[mt][1] = As[cur][(rb + g + 8) * ALD + ks + tig];
                afr[mt][2] = As[cur][(rb + g)     * ALD + ks + tig + 4];
                afr[mt][3] = As[cur][(rb + g + 8) * ALD + ks + tig + 4];
            }
#pragma unroll
            for (int nt = 0; nt < 4; nt++) {
                int nb = wn + nt * 8;
                bfr[nt][0] = Bs[cur][(ks + tig)     * BLD + nb + g];
                bfr[nt][1] = Bs[cur][(ks + tig + 4) * BLD + nb + g];
            }
#pragma unroll
            for (int mt = 0; mt < 4; mt++)
#pragma unroll
                for (int nt = 0; nt < 4; nt++)
                    mma_tf32_v(acc[mt][nt], afr[mt][0], afr[mt][1], afr[mt][2], afr[mt][3],
                               bfr[nt][0], bfr[nt][1]);
        }
        if (t + 1 < ntiles) {
            int nxt = cur ^ 1;
#pragma unroll
            for (int i = 0; i < 2; i++) {
                float* as = &As[nxt][a_row[i] * ALD + a_kq[i]];
                as[0] = to_tf32(av[i].x); as[1] = to_tf32(av[i].y);
                as[2] = to_tf32(av[i].z); as[3] = to_tf32(av[i].w);
                float* bs = &Bs[nxt][b_kr[i] * BLD + b_nq[i]];
                bs[0] = to_tf32(bv[i].x); bs[1] = to_tf32(bv[i].y);
                bs[2] = to_tf32(bv[i].z); bs[3] = to_tf32(bv[i].w);
            }
        }
        __syncthreads();
    }

#pragma unroll
    for (int mt = 0; mt < 4; mt++) {
        int gm0 = bm * 128 + wm + mt * 16 + g;
        int gm1 = gm0 + 8;
        int cr0 = (gm0 / c_per) * c_span + c_base + (gm0 % c_per);
        int cr1 = (gm1 / c_per) * c_span + c_base + (gm1 % c_per);
#pragma unroll
        for (int nt = 0; nt < 4; nt++) {
            int cn = bn * 128 + wn + nt * 8 + 2 * tig;
            float2 bi = *(const float2*)(bias + cn);
            *(float2*)(C + (size_t)cr0 * N + cn) =
                make_float2(acc[mt][nt][0] + bi.x, acc[mt][nt][1] + bi.y);
            *(float2*)(C + (size_t)cr1 * N + cn) =
                make_float2(acc[mt][nt][2] + bi.x, acc[mt][nt][3] + bi.y);
        }
    }
}

// =====================================================================
// Flash attention (unchanged from R10 winner).
// =====================================================================
#define QP_F   (8 * 128 * 8)
#define KP_F   4096
#define VP_F   4096
#define KBUF_OFF(i) ((i) * 4096)
#define VBUF_OFF(i) (8192 + (i) * 4096)
#define ATTN_SMEM (16384 * 4)
__global__ __launch_bounds__(128, 2) void attn_kernel()
{
    extern __shared__ float sm[];

    int qt = blockIdx.x;
    int bh = blockIdx.y;
    int tid = threadIdx.x;
    int warp = tid >> 5, lane = tid & 31;
    int g = lane >> 2, tig = lane & 3;
    int mb = warp * 32;

    uint32_t smb = (uint32_t)__cvta_generic_to_shared(sm);

    const float* Qg = g_qp + ((size_t)bh * NQT + qt) * QP_F;
    const float* Kg = g_kp + (size_t)bh * NKT * KP_F;
    const float* Vg = g_vp + (size_t)bh * NKT * VP_F;

#pragma unroll
    for (int i = 0; i < 8; i++) {
        int c = (tid + i * 128) * 4;
        cp16(smb + (KBUF_OFF(0) + c) * 4, Kg + c);
        cp16(smb + (VBUF_OFF(0) + c) * 4, Vg + c);
    }
    CP_COMMIT();
#pragma unroll
    for (int i = 0; i < 8; i++) {
        int c = (tid + i * 128) * 4;
        cp16(smb + (KBUF_OFF(1) + c) * 4, Kg + KP_F + c);
        cp16(smb + (VBUF_OFF(1) + c) * 4, Vg + VP_F + c);
    }
    CP_COMMIT();

    float2 qf[8][4];
#pragma unroll
    for (int ks = 0; ks < 8; ks++) {
        const float* qb = Qg + ks * 1024;
        qf[ks][0] = *(const float2*)&qb[(mb + g)      * 8 + 2 * tig];
        qf[ks][1] = *(const float2*)&qb[(mb + g + 8)  * 8 + 2 * tig];
        qf[ks][2] = *(const float2*)&qb[(mb + g + 16) * 8 + 2 * tig];
        qf[ks][3] = *(const float2*)&qb[(mb + g + 24) * 8 + 2 * tig];
    }

    float S[2][8][4], O[2][8][4];
    float ls[2][2];
#pragma unroll
    for (int f = 0; f < 2; f++) {
#pragma unroll
        for (int nt = 0; nt < 8; nt++)
#pragma unroll
            for (int r = 0; r < 4; r++) O[f][nt][r] = 0.f;
        ls[f][0] = ls[f][1] = 0.f;
    }

    for (int kt = 0; kt < NKT; kt++) {
        int cur = kt & 1;
        const float* Kp = sm + KBUF_OFF(cur);
        const float* Vs = sm + VBUF_OFF(cur);

        CP_WAIT1();
        __syncthreads();

#pragma unroll
        for (int f = 0; f < 2; f++)
#pragma unroll
            for (int nt = 0; nt < 8; nt++)
#pragma unroll
                for (int r = 0; r < 4; r++) S[f][nt][r] = 0.f;
#pragma unroll
        for (int ks = 0; ks < 8; ks++) {
            const float* kb = Kp + ks * 512;
            float2 a0 = qf[ks][0], a1 = qf[ks][1];
            float2 a2 = qf[ks][2], a3 = qf[ks][3];
#pragma unroll
            for (int nt = 0; nt < 8; nt++) {
                float2 b = *(const float2*)&kb[(nt * 8 + g) * 8 + 2 * tig];
                mma_tf32_v(S[0][nt], a0.x, a1.x, a0.y, a1.y, b.x, b.y);
                mma_tf32_v(S[1][nt], a2.x, a3.x, a2.y, a3.y, b.x, b.y);
            }
        }

        float biasv = (qt < 16 && kt < 32 && (kt >> 2) > (qt >> 1)) ? 1.0f : 0.0f;

#pragma unroll
        for (int f = 0; f < 2; f++) {
            float s0 = 0.f, s1 = 0.f;
#pragma unroll
            for (int nt = 0; nt < 8; nt++) {
                float p0 = __expf(S[f][nt][0] + biasv);
                float p1 = __expf(S[f][nt][1] + biasv);
                float p2 = __expf(S[f][nt][2] + biasv);
                float p3 = __expf(S[f][nt][3] + biasv);
                S[f][nt][0] = p0; S[f][nt][1] = p1;
                S[f][nt][2] = p2; S[f][nt][3] = p3;
                s0 += p0 + p1;
                s1 += p2 + p3;
            }
            ls[f][0] += s0;
            ls[f][1] += s1;
        }

#pragma unroll
        for (int kc = 0; kc < 8; kc++) {
            const float* vb = Vs + kc * 512 + 2 * tig;
            float a00 = to_tf32(S[0][kc][0]);
            float a01 = to_tf32(S[0][kc][2]);
            float a02 = to_tf32(S[0][kc][1]);
            float a03 = to_tf32(S[0][kc][3]);
            float a10 = to_tf32(S[1][kc][0]);
            float a11 = to_tf32(S[1][kc][2]);
            float a12 = to_tf32(S[1][kc][1]);
            float a13 = to_tf32(S[1][kc][3]);
#pragma unroll
            for (int nt = 0; nt < 8; nt++) {
                float2 b = *(const float2*)&vb[(nt * 8 + g) * 8];
                mma_tf32_v(O[0][nt], a00, a01, a02, a03, b.x, b.y);
                mma_tf32_v(O[1][nt], a10, a11, a12, a13, b.x, b.y);
            }
        }

        __syncthreads();
        if (kt + 2 < NKT) {
#pragma unroll
            for (int i = 0; i < 8; i++) {
                int c = (tid + i * 128) * 4;
                cp16(smb + (KBUF_OFF(cur) + c) * 4, Kg + (size_t)(kt + 2) * KP_F + c);
                cp16(smb + (VBUF_OFF(cur) + c) * 4, Vg + (size_t)(kt + 2) * VP_F + c);
            }
        }
        CP_COMMIT();
    }

#pragma unroll
    for (int f = 0; f < 2; f++)
#pragma unroll
        for (int r = 0; r < 2; r++) {
            ls[f][r] += __shfl_xor_sync(0xffffffffu, ls[f][r], 1);
            ls[f][r] += __shfl_xor_sync(0xffffffffu, ls[f][r], 2);
        }

    int b = bh / HH, h = bh % HH;
#pragma unroll
    for (int f = 0; f < 2; f++) {
        float inv0 = 1.f / ls[f][0], inv1 = 1.f / ls[f][1];
        int t0 = qt * QTR + mb + f * 16 + g;
#pragma unroll
        for (int nt = 0; nt < 8; nt++) {
            int col = h * DHH + nt * 8 + 2 * tig;
            *(float2*)(g_x + (size_t)(b * TT + t0) * DD + col) =
                make_float2(O[f][nt][0] * inv0, O[f][nt][1] * inv0);
            *(float2*)(g_x + (size_t)(b * TT + t0 + 8) * DD + col) =
                make_float2(O[f][nt][2] * inv1, O[f][nt][3] * inv1);
        }
    }
}

// =====================================================================
// Launch
// =====================================================================
extern "C" void kernel_launch(void* const* d_in, const int* in_sizes, int n_in,
                              void* d_out, int out_size)
{
    const float* x1    = (const float*)d_in[0];
    const float* x2    = (const float*)d_in[1];
    const float* Wqkv1 = (const float*)d_in[2];
    const float* bqkv1 = (const float*)d_in[3];
    const float* Wqkv2 = (const float*)d_in[4];
    const float* bqkv2 = (const float*)d_in[5];
    const float* Wout1 = (const float*)d_in[6];
    const float* bout1 = (const float*)d_in[7];
    const float* Wout2 = (const float*)d_in[8];
    const float* bout2 = (const float*)d_in[9];
    const float* gq1   = (const float*)d_in[10];
    const float* gk1   = (const float*)d_in[11];
    const float* gq2   = (const float*)d_in[12];
    const float* gk2   = (const float*)d_in[13];
    float* out = (float*)d_out;

    float* p_x = nullptr;
    cudaGetSymbolAddress((void**)&p_x, g_x);

    // QKV GEMM + fused RMSNorm + packed scatter (x1: 32 row-tiles, x2: 2)
    qkv_gemm_fused<<<dim3(ND3 / 128, 34), 256>>>(
        x1, Wqkv1, bqkv1,
        x2, Wqkv2, bqkv2,
        gq1, gk1, gq2, gk2);

    // Attention
    cudaFuncSetAttribute(attn_kernel, cudaFuncAttributeMaxDynamicSharedMemorySize, ATTN_SMEM);
    attn_kernel<<<dim3(NQT, BB * HH), 128, ATTN_SMEM>>>();

    // Output projections (out1: 32 tiles, out2: 2 tiles, merged)
    sgemm_tf32_dual<<<dim3(DD / 128, 34), 256>>>(
        p_x, Wout1, bout1, out,
        p_x, Wout2, bout2, out + (size_t)BB * N1L * DD,
        DD, DD, 32,
        N1L, 0, TT,        BB * N1L, 0, BB * N1L,
        N2L, N1L, TT,      BB * N2L, 0, BB * N2L);
}